// round 8
// baseline (speedup 1.0000x reference)
#include <cuda_runtime.h>
#include <cuda_fp16.h>
#include <math.h>
#include <cfloat>
#include <stdint.h>

// ---------------- problem dims (fixed) ----------------
#define NTOT  65536      // nodes per side (B*N)
#define NEDGE 524288     // edges per side
#define NB    128        // graphs
#define NPG   512        // nodes per graph
#define D_F1  128
#define D_F2  96
#define D_F3  64
#define D_BINS 16

// ---------------- device scratch (per-side slabs for batched launches) -----
__device__ float g_bufA[2][NTOT * D_F1];
__device__ float g_bufB[2][NTOT * D_F1];
__device__ float g_feat[2][NTOT * D_F3];
__device__ float g_dinv[2][NTOT];
__device__ int   g_degi[2][NTOT];
__device__ int   g_row[2][NTOT + 1];
__device__ int   g_cursor[2][NTOT];
__device__ int   g_bsum[2][256];
__device__ int   g_boff[2][256];
__device__ int   g_esrc[2][NEDGE];
__device__ float g_enorm[2][NEDGE];
__device__ __half g_simh[(size_t)NB * NPG * NPG];   // fp16 similarity scores
__device__ int   g_hist[NB * D_BINS];
__device__ float g_smin[NB];
__device__ float g_smax[NB];
__device__ float g_pool[2][NB * D_F3];

__device__ __forceinline__ float sigmoidf_(float x) { return 1.0f / (1.0f + expf(-x)); }

__device__ __forceinline__ void atomicMinFloat(float* addr, float val) {
    int old = __float_as_int(*addr);
    while (__int_as_float(old) > val) {
        int assumed = old;
        old = atomicCAS((int*)addr, assumed, __float_as_int(val));
        if (old == assumed) break;
    }
}
__device__ __forceinline__ void atomicMaxFloat(float* addr, float val) {
    int old = __float_as_int(*addr);
    while (__int_as_float(old) < val) {
        int assumed = old;
        old = atomicCAS((int*)addr, assumed, __float_as_int(val));
        if (old == assumed) break;
    }
}

// ---------------- tf32 helpers (3xTF32 fp32-emulation split) ----------------
__device__ __forceinline__ uint32_t f2tf32(float x) {
    uint32_t r;
    asm("cvt.rna.tf32.f32 %0, %1;" : "=r"(r) : "f"(x));
    return r;
}
__device__ __forceinline__ void split_tf32(float x, uint32_t& hi, uint32_t& lo) {
    hi = f2tf32(x);
    lo = f2tf32(x - __uint_as_float(hi));
}
__device__ __forceinline__ void mma_tf32(float* d, const uint32_t* a, const uint32_t* b) {
    asm volatile(
        "mma.sync.aligned.m16n8k8.row.col.f32.tf32.tf32.f32 "
        "{%0,%1,%2,%3}, {%4,%5,%6,%7}, {%8,%9}, {%0,%1,%2,%3};\n"
        : "+f"(d[0]), "+f"(d[1]), "+f"(d[2]), "+f"(d[3])
        : "r"(a[0]), "r"(a[1]), "r"(a[2]), "r"(a[3]), "r"(b[0]), "r"(b[1]));
}

// block-wide exclusive scan of 256 ints (one value per thread)
__device__ __forceinline__ int block_exscan_256(int v, int* sm8) {
    int lane = threadIdx.x & 31, w = threadIdx.x >> 5;
    int x = v;
#pragma unroll
    for (int o = 1; o < 32; o <<= 1) {
        int y = __shfl_up_sync(0xffffffffu, x, o);
        if (lane >= o) x += y;
    }
    if (lane == 31) sm8[w] = x;
    __syncthreads();
    if (threadIdx.x < 8) {
        int s = sm8[threadIdx.x];
#pragma unroll
        for (int o = 1; o < 8; o <<= 1) {
            int y = __shfl_up_sync(0xffu, s, o);
            if ((int)threadIdx.x >= o) s += y;
        }
        sm8[threadIdx.x] = s;
    }
    __syncthreads();
    int woff = w ? sm8[w - 1] : 0;
    return woff + x - v;
}

// ---------------- init ----------------
__global__ void init_k() {
    int i = blockIdx.x * blockDim.x + threadIdx.x;
    if (i < NTOT) { g_degi[0][i] = 0; g_degi[1][i] = 0; }
    if (i < NB) { g_smin[i] = FLT_MAX; g_smax[i] = -FLT_MAX; }
}

// ---------------- degree (both sides via grid.y) ----------------
__global__ void deg_k(const int* __restrict__ dst0, const int* __restrict__ dst1) {
    int side = blockIdx.y;
    const int* dst = side ? dst1 : dst0;
    int e = blockIdx.x * blockDim.x + threadIdx.x;
    if (e < NEDGE) atomicAdd(&g_degi[side][dst[e]], 1);
}

// ---------------- 3-phase parallel scan (A also computes dinv) -------------
__global__ void scanA_k() {
    int side = blockIdx.y;
    int i = blockIdx.x * 256 + threadIdx.x;
    int v = g_degi[side][i];
    g_dinv[side][i] = rsqrtf((float)v + 1.0f);
#pragma unroll
    for (int o = 16; o; o >>= 1) v += __shfl_xor_sync(0xffffffffu, v, o);
    __shared__ int sm[8];
    if ((threadIdx.x & 31) == 0) sm[threadIdx.x >> 5] = v;
    __syncthreads();
    if (threadIdx.x == 0) {
        int s = 0;
#pragma unroll
        for (int j = 0; j < 8; j++) s += sm[j];
        g_bsum[side][blockIdx.x] = s;
    }
}
__global__ void scanB_k() {
    int side = blockIdx.x;
    __shared__ int sm[8];
    int v = g_bsum[side][threadIdx.x];
    int ex = block_exscan_256(v, sm);
    g_boff[side][threadIdx.x] = ex + v;
}
__global__ void scanC_k() {
    int side = blockIdx.y;
    int i = blockIdx.x * 256 + threadIdx.x;
    int d = g_degi[side][i];
    __shared__ int sm[8];
    int ex = block_exscan_256(d, sm);
    int off = (blockIdx.x ? g_boff[side][blockIdx.x - 1] : 0) + ex;
    g_row[side][i] = off;
    g_cursor[side][i] = off;
    if (i == NTOT - 1) g_row[side][NTOT] = NEDGE;
}

// ---------------- scatter edges into CSR order ----------------
__global__ void scatter_k(const int* __restrict__ ei0, const int* __restrict__ ei1) {
    int side = blockIdx.y;
    const int* ei = side ? ei1 : ei0;
    const int* src = ei;
    const int* dst = ei + NEDGE;
    int e = blockIdx.x * blockDim.x + threadIdx.x;
    if (e >= NEDGE) return;
    int s = src[e], d = dst[e];
    int pos = atomicAdd(&g_cursor[side][d], 1);
    g_esrc[side][pos] = s;
    g_enorm[side][pos] = g_dinv[side][s] * g_dinv[side][d];
}

// ---------------- gather-based aggregation (both sides via grid.y) --------
template <int OUT, bool BIAS, bool RELU>
__global__ void agg_k(const float* __restrict__ xw0, const float* __restrict__ xw1,
                      const float* __restrict__ bias,
                      float* __restrict__ out0, float* __restrict__ out1) {
    constexpr int C4 = OUT / 4;
    int side = blockIdx.y;
    const float* xw = side ? xw1 : xw0;
    float* out = side ? out1 : out0;
    int gid = blockIdx.x * blockDim.x + threadIdx.x;
    int node = gid / C4, chunk = gid % C4;
    if (node >= NTOT) return;
    const float4* xw4 = (const float4*)xw;
    float dv = g_dinv[side][node];
    float dv2 = dv * dv;
    float4 v = xw4[(size_t)node * C4 + chunk];
    float4 acc = make_float4(v.x * dv2, v.y * dv2, v.z * dv2, v.w * dv2);
    int beg = g_row[side][node], end = g_row[side][node + 1];
    for (int e = beg; e < end; e++) {
        int s = g_esrc[side][e];
        float nm = g_enorm[side][e];
        float4 u = xw4[(size_t)s * C4 + chunk];
        acc.x += u.x * nm; acc.y += u.y * nm; acc.z += u.z * nm; acc.w += u.w * nm;
    }
    if (BIAS) {
        acc.x += bias[chunk * 4 + 0];
        acc.y += bias[chunk * 4 + 1];
        acc.z += bias[chunk * 4 + 2];
        acc.w += bias[chunk * 4 + 3];
    }
    if (RELU) {
        acc.x = fmaxf(acc.x, 0.f); acc.y = fmaxf(acc.y, 0.f);
        acc.z = fmaxf(acc.z, 0.f); acc.w = fmaxf(acc.w, 0.f);
    }
    ((float4*)out)[(size_t)node * C4 + chunk] = acc;
}

// ---------------- 3xTF32 tensor-core GEMM (both sides via grid.y) ----------
template <int KIN, int NOUT, bool BIAS, bool RELU>
__global__ void gemm_mma_k(const float* __restrict__ x0, const float* __restrict__ x1,
                           const float* __restrict__ W, const float* __restrict__ bias,
                           float* __restrict__ out0, float* __restrict__ out1) {
    constexpr int KC = 16;
    constexpr int NT = NOUT / 8;
    constexpr int XS = KC + 4;
    constexpr int WS = NOUT + 8;
    __shared__ uint32_t Xh[128 * XS];
    __shared__ uint32_t Xl[128 * XS];
    __shared__ uint32_t Wh[KC * WS];
    __shared__ uint32_t Wl[KC * WS];
    int side = blockIdx.y;
    const float* x = side ? x1 : x0;
    float* out = side ? out1 : out0;
    int tid = threadIdx.x;
    int warp = tid >> 5, lane = tid & 31;
    size_t m0 = (size_t)blockIdx.x * 128;
    float acc[NT][4];
#pragma unroll
    for (int i = 0; i < NT; i++)
#pragma unroll
        for (int j = 0; j < 4; j++) acc[i][j] = 0.0f;

    for (int k0 = 0; k0 < KIN; k0 += KC) {
        for (int i = tid; i < 128 * (KC / 4); i += 256) {
            int r = i / (KC / 4), q = i % (KC / 4);
            float4 v = *(const float4*)&x[(m0 + r) * KIN + k0 + q * 4];
            uint32_t* ph = &Xh[r * XS + q * 4];
            uint32_t* pl = &Xl[r * XS + q * 4];
            split_tf32(v.x, ph[0], pl[0]); split_tf32(v.y, ph[1], pl[1]);
            split_tf32(v.z, ph[2], pl[2]); split_tf32(v.w, ph[3], pl[3]);
        }
        for (int i = tid; i < KC * NOUT / 4; i += 256) {
            int k = i / (NOUT / 4), q = i % (NOUT / 4);
            float4 v = *(const float4*)&W[(size_t)(k0 + k) * NOUT + q * 4];
            uint32_t* ph = &Wh[k * WS + q * 4];
            uint32_t* pl = &Wl[k * WS + q * 4];
            split_tf32(v.x, ph[0], pl[0]); split_tf32(v.y, ph[1], pl[1]);
            split_tf32(v.z, ph[2], pl[2]); split_tf32(v.w, ph[3], pl[3]);
        }
        __syncthreads();
#pragma unroll
        for (int ks = 0; ks < KC / 8; ks++) {
            uint32_t ah[4], al[4];
            int arow = warp * 16 + (lane >> 2);
            int acol = ks * 8 + (lane & 3);
            ah[0] = Xh[arow * XS + acol];       al[0] = Xl[arow * XS + acol];
            ah[1] = Xh[(arow + 8) * XS + acol]; al[1] = Xl[(arow + 8) * XS + acol];
            ah[2] = Xh[arow * XS + acol + 4];   al[2] = Xl[arow * XS + acol + 4];
            ah[3] = Xh[(arow + 8) * XS + acol + 4]; al[3] = Xl[(arow + 8) * XS + acol + 4];
            int bk = ks * 8 + (lane & 3);
            int bn0 = lane >> 2;
#pragma unroll
            for (int nt = 0; nt < NT; nt++) {
                uint32_t bh[2], bl[2];
                bh[0] = Wh[bk * WS + nt * 8 + bn0];
                bh[1] = Wh[(bk + 4) * WS + nt * 8 + bn0];
                bl[0] = Wl[bk * WS + nt * 8 + bn0];
                bl[1] = Wl[(bk + 4) * WS + nt * 8 + bn0];
                mma_tf32(acc[nt], ah, bh);
                mma_tf32(acc[nt], ah, bl);
                mma_tf32(acc[nt], al, bh);
            }
        }
        __syncthreads();
    }
    size_t row = m0 + warp * 16 + (lane >> 2);
    int col0 = (lane & 3) * 2;
#pragma unroll
    for (int nt = 0; nt < NT; nt++) {
        int c = nt * 8 + col0;
        float b0 = BIAS ? bias[c] : 0.0f, b1 = BIAS ? bias[c + 1] : 0.0f;
        float v0 = acc[nt][0] + b0, v1 = acc[nt][1] + b1;
        float v2 = acc[nt][2] + b0, v3 = acc[nt][3] + b1;
        if (RELU) {
            v0 = fmaxf(v0, 0.f); v1 = fmaxf(v1, 0.f);
            v2 = fmaxf(v2, 0.f); v3 = fmaxf(v3, 0.f);
        }
        *(float2*)&out[row * NOUT + c] = make_float2(v0, v1);
        *(float2*)&out[(row + 8) * NOUT + c] = make_float2(v2, v3);
    }
}

// ---------------- attention pooling (grid = (NB, 2)) ----------------
__global__ void pool_k(const float* __restrict__ Watt) {
    int side = blockIdx.y;
    int b = blockIdx.x;
    const float* fb = &g_feat[side][(size_t)b * NPG * D_F3];
    int t = threadIdx.x;  // 256
    __shared__ float p4[4][64];
    __shared__ float meanc[64];
    __shared__ float ctx[64];
    __shared__ float wsum[8][64];
    int d = t & 63, g = t >> 6;
    float loc = 0.0f;
    for (int r = g; r < NPG; r += 4) loc += fb[r * 64 + d];
    p4[g][d] = loc;
    __syncthreads();
    if (t < 64) meanc[t] = (p4[0][t] + p4[1][t] + p4[2][t] + p4[3][t]) * (1.0f / NPG);
    __syncthreads();
    if (t < 64) {
        float c = 0.0f;
        for (int i = 0; i < 64; i++) c += meanc[i] * Watt[i * 64 + t];
        ctx[t] = tanhf(c);
    }
    __syncthreads();
    int w = t >> 5, l = t & 31;
    float a0 = 0.0f, a1 = 0.0f;
    float c0 = ctx[l], c1 = ctx[l + 32];
    for (int r = w * 64; r < w * 64 + 64; r++) {
        float v0 = fb[r * 64 + l], v1 = fb[r * 64 + 32 + l];
        float dp = v0 * c0 + v1 * c1;
#pragma unroll
        for (int o = 16; o; o >>= 1) dp += __shfl_xor_sync(0xffffffffu, dp, o);
        float coef = sigmoidf_(dp);
        a0 += v0 * coef;
        a1 += v1 * coef;
    }
    wsum[w][l] = a0;
    wsum[w][l + 32] = a1;
    __syncthreads();
    if (t < 64) {
        float s = 0.0f;
        for (int w2 = 0; w2 < 8; w2++) s += wsum[w2][t];
        g_pool[side][b * 64 + t] = s;
    }
}

// ---------------- similarity via 3xTF32 mma, 128x128 tile, fp16 store ------
__global__ void sim_mma_k() {
    constexpr int KC = 16;
    constexpr int XS = KC + 4;
    int b = blockIdx.z;
    int i0 = blockIdx.y * 128, j0 = blockIdx.x * 128;
    __shared__ uint32_t Ah_s[128 * XS];
    __shared__ uint32_t Al_s[128 * XS];
    __shared__ uint32_t Bh_s[128 * XS];
    __shared__ uint32_t Bl_s[128 * XS];
    const float* f1 = &g_feat[0][(size_t)(b * NPG + i0) * 64];
    const float* f2 = &g_feat[1][(size_t)(b * NPG + j0) * 64];
    int tid = threadIdx.x;
    int warp = tid >> 5, lane = tid & 31;
    int wm = warp >> 2, wn = warp & 3;
    float acc[4][4][4];
#pragma unroll
    for (int mt = 0; mt < 4; mt++)
#pragma unroll
        for (int nt = 0; nt < 4; nt++)
#pragma unroll
            for (int j = 0; j < 4; j++) acc[mt][nt][j] = 0.0f;

    for (int k0 = 0; k0 < 64; k0 += KC) {
        for (int i = tid; i < 128 * (KC / 4); i += 256) {
            int r = i / (KC / 4), q = i % (KC / 4);
            float4 va = *(const float4*)&f1[r * 64 + k0 + q * 4];
            float4 vb = *(const float4*)&f2[r * 64 + k0 + q * 4];
            uint32_t* pah = &Ah_s[r * XS + q * 4];
            uint32_t* pal = &Al_s[r * XS + q * 4];
            uint32_t* pbh = &Bh_s[r * XS + q * 4];
            uint32_t* pbl = &Bl_s[r * XS + q * 4];
            split_tf32(va.x, pah[0], pal[0]); split_tf32(va.y, pah[1], pal[1]);
            split_tf32(va.z, pah[2], pal[2]); split_tf32(va.w, pah[3], pal[3]);
            split_tf32(vb.x, pbh[0], pbl[0]); split_tf32(vb.y, pbh[1], pbl[1]);
            split_tf32(vb.z, pbh[2], pbl[2]); split_tf32(vb.w, pbh[3], pbl[3]);
        }
        __syncthreads();
#pragma unroll
        for (int ks = 0; ks < KC / 8; ks++) {
            int acol = ks * 8 + (lane & 3);
            uint32_t ah[4][4], al[4][4], bh[4][2], bl[4][2];
#pragma unroll
            for (int mt = 0; mt < 4; mt++) {
                int arow = wm * 64 + mt * 16 + (lane >> 2);
                ah[mt][0] = Ah_s[arow * XS + acol];
                ah[mt][1] = Ah_s[(arow + 8) * XS + acol];
                ah[mt][2] = Ah_s[arow * XS + acol + 4];
                ah[mt][3] = Ah_s[(arow + 8) * XS + acol + 4];
                al[mt][0] = Al_s[arow * XS + acol];
                al[mt][1] = Al_s[(arow + 8) * XS + acol];
                al[mt][2] = Al_s[arow * XS + acol + 4];
                al[mt][3] = Al_s[(arow + 8) * XS + acol + 4];
            }
#pragma unroll
            for (int nt = 0; nt < 4; nt++) {
                int bnode = wn * 32 + nt * 8 + (lane >> 2);
                bh[nt][0] = Bh_s[bnode * XS + acol];
                bh[nt][1] = Bh_s[bnode * XS + acol + 4];
                bl[nt][0] = Bl_s[bnode * XS + acol];
                bl[nt][1] = Bl_s[bnode * XS + acol + 4];
            }
#pragma unroll
            for (int mt = 0; mt < 4; mt++)
#pragma unroll
                for (int nt = 0; nt < 4; nt++) {
                    mma_tf32(acc[mt][nt], ah[mt], bh[nt]);
                    mma_tf32(acc[mt][nt], ah[mt], bl[nt]);
                    mma_tf32(acc[mt][nt], al[mt], bh[nt]);
                }
        }
        __syncthreads();
    }
    float lmin = FLT_MAX, lmax = -FLT_MAX;
    __half* sp = &g_simh[(size_t)b * NPG * NPG];
    int col0 = (lane & 3) * 2;
#pragma unroll
    for (int mt = 0; mt < 4; mt++) {
        size_t r0 = (size_t)(i0 + wm * 64 + mt * 16 + (lane >> 2));
#pragma unroll
        for (int nt = 0; nt < 4; nt++) {
            int c = j0 + wn * 32 + nt * 8 + col0;
            float v0 = acc[mt][nt][0], v1 = acc[mt][nt][1];
            float v2 = acc[mt][nt][2], v3 = acc[mt][nt][3];
            lmin = fminf(lmin, fminf(fminf(v0, v1), fminf(v2, v3)));
            lmax = fmaxf(lmax, fmaxf(fmaxf(v0, v1), fmaxf(v2, v3)));
            *(__half2*)&sp[r0 * NPG + c] = __floats2half2_rn(v0, v1);
            *(__half2*)&sp[(r0 + 8) * NPG + c] = __floats2half2_rn(v2, v3);
        }
    }
    __shared__ float rmin[256], rmax[256];
    rmin[tid] = lmin;
    rmax[tid] = lmax;
    __syncthreads();
    for (int s = 128; s > 0; s >>= 1) {
        if (tid < s) {
            rmin[tid] = fminf(rmin[tid], rmin[tid + s]);
            rmax[tid] = fmaxf(rmax[tid], rmax[tid + s]);
        }
        __syncthreads();
    }
    if (tid == 0) {
        atomicMinFloat(&g_smin[b], rmin[0]);
        atomicMaxFloat(&g_smax[b], rmax[0]);
    }
}

// ---------------- histogram via threshold CDF + warp ballot ----------------
// grid = NB blocks, 512 threads. No sigmoid per value: bin boundaries are
// inverted once per graph (thr_k = logit(vmin + k*width)), then each value
// only needs 15 compares counted via ballot/popc.
__global__ void hist_k() {
    int b = blockIdx.x;
    int t = threadIdx.x;
    int lane = t & 31, warp = t >> 5;    // 16 warps
    __shared__ float thr_s[15];
    __shared__ int cnt_s[16][16];
    if (t < 15) {
        float vmin = sigmoidf_(g_smin[b]);
        float vmax = sigmoidf_(g_smax[b]);
        float width = (vmax - vmin) * (1.0f / D_BINS);
        if (width > 0.0f) {
            float bnd = vmin + (float)(t + 1) * width;   // boundary k = t+1
            thr_s[t] = logf(bnd / (1.0f - bnd));
        } else {
            thr_s[t] = FLT_MAX;                           // all values -> bin 0
        }
    }
    __syncthreads();
    float T[15];
#pragma unroll
    for (int k = 0; k < 15; k++) T[k] = thr_s[k];

    const uint4* qp = (const uint4*)&g_simh[(size_t)b * NPG * NPG];
    const int NQ = NPG * NPG / 8;       // 8 halfs per uint4
    int cnt = 0;                         // lane k (<15) counts s >= thr_k
    for (int i = t; i < NQ; i += 512) {
        uint4 q = qp[i];
        float2 p0 = __half22float2(*(__half2*)&q.x);
        float2 p1 = __half22float2(*(__half2*)&q.y);
        float2 p2 = __half22float2(*(__half2*)&q.z);
        float2 p3 = __half22float2(*(__half2*)&q.w);
        float v[8] = {p0.x, p0.y, p1.x, p1.y, p2.x, p2.y, p3.x, p3.y};
#pragma unroll
        for (int k = 0; k < 15; k++) {
            int c = 0;
#pragma unroll
            for (int j = 0; j < 8; j++)
                c += __popc(__ballot_sync(0xffffffffu, v[j] >= T[k]));
            if (lane == k) cnt += c;
        }
    }
    if (lane < 16) cnt_s[warp][lane] = cnt;   // lane 15 stores 0-init garbage? no: cnt stays 0 for lane 15
    __syncthreads();
    if (t < 15) {
        int s = 0;
#pragma unroll
        for (int w = 0; w < 16; w++) s += cnt_s[w][t];
        cnt_s[0][t] = s;                      // C[k] = count(s >= thr_{k+1})
    }
    __syncthreads();
    if (t < D_BINS) {
        int C_lo = (t == 0) ? NPG * NPG : cnt_s[0][t - 1];
        int C_hi = (t == 15) ? 0 : cnt_s[0][t];
        g_hist[b * D_BINS + t] = C_lo - C_hi;
    }
}

// ---------------- final head (one block per graph, 128 threads) ----------
__global__ void final_k(const float* __restrict__ Wt, const float* __restrict__ Wtb,
                        const float* __restrict__ tb, const float* __restrict__ W1,
                        const float* __restrict__ b1, const float* __restrict__ Ws,
                        const float* __restrict__ bs, float* __restrict__ out) {
    int b = blockIdx.x, t = threadIdx.x;
    __shared__ float p1s[64], p2s[64];
    __shared__ float scp[64 * 16];
    __shared__ float feat[32];
    __shared__ float hs[32];
    if (t < 64) {
        p1s[t] = g_pool[0][b * 64 + t];
        p2s[t] = g_pool[1][b * 64 + t];
    }
    __syncthreads();
    if (t < 64) {
        float s[16];
#pragma unroll
        for (int k = 0; k < 16; k++) s[k] = 0.0f;
        for (int j = 0; j < 64; j++) {
            float pj = p2s[j];
            const float* wp = &Wt[(size_t)(t * 64 + j) * 16];
#pragma unroll
            for (int k = 0; k < 16; k++) s[k] += wp[k] * pj;
        }
        float p1v = p1s[t];
#pragma unroll
        for (int k = 0; k < 16; k++) scp[t * 16 + k] = p1v * s[k];
    }
    __syncthreads();
    if (t < 16) {
        float acc = tb[t];
        for (int i = 0; i < 64; i++) acc += scp[i * 16 + t];
        float blk = 0.0f;
        for (int i = 0; i < 64; i++) blk += Wtb[t * 128 + i] * p1s[i];
        for (int i = 0; i < 64; i++) blk += Wtb[t * 128 + 64 + i] * p2s[i];
        float tv = acc + blk;
        feat[t] = fmaxf(tv, 0.0f);
        feat[16 + t] = (float)g_hist[b * 16 + t] * (1.0f / ((float)NPG * (float)NPG));
    }
    __syncthreads();
    if (t < 32) {
        float acc = b1[t];
        for (int i = 0; i < 32; i++) acc += feat[i] * W1[i * 32 + t];
        hs[t] = fmaxf(acc, 0.0f);
    }
    __syncthreads();
    if (t == 0) {
        float acc = bs[0];
        for (int j = 0; j < 32; j++) acc += hs[j] * Ws[j];
        out[b] = sigmoidf_(acc);
    }
}

// ---------------- launcher ----------------
extern "C" void kernel_launch(void* const* d_in, const int* in_sizes, int n_in,
                              void* d_out, int out_size) {
    const float* x1  = (const float*)d_in[0];
    const float* x2  = (const float*)d_in[1];
    const int* ei1   = (const int*)d_in[2];
    const int* ei2   = (const int*)d_in[3];
    const float* Wc1 = (const float*)d_in[6];
    const float* bc1 = (const float*)d_in[7];
    const float* Wc2 = (const float*)d_in[8];
    const float* bc2 = (const float*)d_in[9];
    const float* Wc3 = (const float*)d_in[10];
    const float* bc3 = (const float*)d_in[11];
    const float* Watt = (const float*)d_in[12];
    const float* Wt  = (const float*)d_in[13];
    const float* Wtb = (const float*)d_in[14];
    const float* tb  = (const float*)d_in[15];
    const float* W1  = (const float*)d_in[16];
    const float* b1  = (const float*)d_in[17];
    const float* Ws  = (const float*)d_in[18];
    const float* bs  = (const float*)d_in[19];
    float* out = (float*)d_out;

    void* p;
    float *a0, *a1, *b0, *b1p, *f0, *f1;
    cudaGetSymbolAddress(&p, g_bufA);
    a0 = (float*)p; a1 = a0 + (size_t)NTOT * D_F1;
    cudaGetSymbolAddress(&p, g_bufB);
    b0 = (float*)p; b1p = b0 + (size_t)NTOT * D_F1;
    cudaGetSymbolAddress(&p, g_feat);
    f0 = (float*)p; f1 = f0 + (size_t)NTOT * D_F3;

    init_k<<<NTOT / 256, 256>>>();

    // CSR build for BOTH sides (batched over grid.y)
    deg_k<<<dim3(NEDGE / 256, 2), 256>>>(ei1 + NEDGE, ei2 + NEDGE);
    scanA_k<<<dim3(256, 2), 256>>>();   // also computes dinv
    scanB_k<<<2, 256>>>();
    scanC_k<<<dim3(256, 2), 256>>>();
    scatter_k<<<dim3(NEDGE / 256, 2), 256>>>(ei1, ei2);

    // conv pipeline, both sides per launch
    agg_k<32, false, false><<<dim3(NTOT * 8 / 256, 2), 256>>>(x1, x2, nullptr, a0, a1);
    gemm_mma_k<32, 128, true, true><<<dim3(NTOT / 128, 2), 256>>>(a0, a1, Wc1, bc1, b0, b1p);

    gemm_mma_k<128, 96, false, false><<<dim3(NTOT / 128, 2), 256>>>(b0, b1p, Wc2, nullptr, a0, a1);
    agg_k<96, true, true><<<dim3(NTOT * 24 / 256, 2), 256>>>(a0, a1, bc2, b0, b1p);

    gemm_mma_k<96, 64, false, false><<<dim3(NTOT / 128, 2), 256>>>(b0, b1p, Wc3, nullptr, a0, a1);
    agg_k<64, true, false><<<dim3(NTOT * 16 / 256, 2), 256>>>(a0, a1, bc3, f0, f1);

    pool_k<<<dim3(NB, 2), 256>>>(Watt);

    sim_mma_k<<<dim3(4, 4, NB), 256>>>();
    hist_k<<<NB, 512>>>();
    final_k<<<NB, 128>>>(Wt, Wtb, tb, W1, b1, Ws, bs, out);
}

// round 9
// speedup vs baseline: 1.1432x; 1.1432x over previous
#include <cuda_runtime.h>
#include <cuda_fp16.h>
#include <math.h>
#include <cfloat>
#include <stdint.h>

// ---------------- problem dims (fixed) ----------------
#define NTOT  65536      // nodes per side (B*N)
#define NEDGE 524288     // edges per side
#define NB    128        // graphs
#define NPG   512        // nodes per graph
#define D_F1  128
#define D_F2  96
#define D_F3  64
#define D_BINS 16

// ---------------- device scratch (per-side slabs for batched launches) -----
__device__ float g_bufA[2][NTOT * D_F1];
__device__ float g_bufB[2][NTOT * D_F1];
__device__ float g_feat[2][NTOT * D_F3];
__device__ float g_dinv[2][NTOT];
__device__ int   g_degi[2][NTOT];
__device__ int   g_row[2][NTOT + 1];
__device__ int   g_cursor[2][NTOT];
__device__ int   g_bsum[2][256];
__device__ int   g_boff[2][256];
__device__ int   g_esrc[2][NEDGE];
__device__ float g_enorm[2][NEDGE];
__device__ __half g_simh[(size_t)NB * NPG * NPG];   // fp16 similarity scores
__device__ int   g_cdf[NB][15];                      // C[k] = #{s >= thr_{k+1}}
__device__ float g_smin[NB];
__device__ float g_smax[NB];
__device__ float g_pool[2][NB * D_F3];

__device__ __forceinline__ float sigmoidf_(float x) { return 1.0f / (1.0f + expf(-x)); }

__device__ __forceinline__ void atomicMinFloat(float* addr, float val) {
    int old = __float_as_int(*addr);
    while (__int_as_float(old) > val) {
        int assumed = old;
        old = atomicCAS((int*)addr, assumed, __float_as_int(val));
        if (old == assumed) break;
    }
}
__device__ __forceinline__ void atomicMaxFloat(float* addr, float val) {
    int old = __float_as_int(*addr);
    while (__int_as_float(old) < val) {
        int assumed = old;
        old = atomicCAS((int*)addr, assumed, __float_as_int(val));
        if (old == assumed) break;
    }
}

// ---------------- tf32 helpers (3xTF32 fp32-emulation split) ----------------
__device__ __forceinline__ uint32_t f2tf32(float x) {
    uint32_t r;
    asm("cvt.rna.tf32.f32 %0, %1;" : "=r"(r) : "f"(x));
    return r;
}
__device__ __forceinline__ void split_tf32(float x, uint32_t& hi, uint32_t& lo) {
    hi = f2tf32(x);
    lo = f2tf32(x - __uint_as_float(hi));
}
__device__ __forceinline__ void mma_tf32(float* d, const uint32_t* a, const uint32_t* b) {
    asm volatile(
        "mma.sync.aligned.m16n8k8.row.col.f32.tf32.tf32.f32 "
        "{%0,%1,%2,%3}, {%4,%5,%6,%7}, {%8,%9}, {%0,%1,%2,%3};\n"
        : "+f"(d[0]), "+f"(d[1]), "+f"(d[2]), "+f"(d[3])
        : "r"(a[0]), "r"(a[1]), "r"(a[2]), "r"(a[3]), "r"(b[0]), "r"(b[1]));
}

// block-wide exclusive scan of 256 ints (one value per thread)
__device__ __forceinline__ int block_exscan_256(int v, int* sm8) {
    int lane = threadIdx.x & 31, w = threadIdx.x >> 5;
    int x = v;
#pragma unroll
    for (int o = 1; o < 32; o <<= 1) {
        int y = __shfl_up_sync(0xffffffffu, x, o);
        if (lane >= o) x += y;
    }
    if (lane == 31) sm8[w] = x;
    __syncthreads();
    if (threadIdx.x < 8) {
        int s = sm8[threadIdx.x];
#pragma unroll
        for (int o = 1; o < 8; o <<= 1) {
            int y = __shfl_up_sync(0xffu, s, o);
            if ((int)threadIdx.x >= o) s += y;
        }
        sm8[threadIdx.x] = s;
    }
    __syncthreads();
    int woff = w ? sm8[w - 1] : 0;
    return woff + x - v;
}

// ---------------- init ----------------
__global__ void init_k() {
    int i = blockIdx.x * blockDim.x + threadIdx.x;
    if (i < NTOT) { g_degi[0][i] = 0; g_degi[1][i] = 0; }
    if (i < NB * 15) g_cdf[i / 15][i % 15] = 0;
    if (i < NB) { g_smin[i] = FLT_MAX; g_smax[i] = -FLT_MAX; }
}

// ---------------- degree (both sides via grid.y) ----------------
__global__ void deg_k(const int* __restrict__ dst0, const int* __restrict__ dst1) {
    int side = blockIdx.y;
    const int* dst = side ? dst1 : dst0;
    int e = blockIdx.x * blockDim.x + threadIdx.x;
    if (e < NEDGE) atomicAdd(&g_degi[side][dst[e]], 1);
}

// ---------------- 3-phase parallel scan (A also computes dinv) -------------
__global__ void scanA_k() {
    int side = blockIdx.y;
    int i = blockIdx.x * 256 + threadIdx.x;
    int v = g_degi[side][i];
    g_dinv[side][i] = rsqrtf((float)v + 1.0f);
#pragma unroll
    for (int o = 16; o; o >>= 1) v += __shfl_xor_sync(0xffffffffu, v, o);
    __shared__ int sm[8];
    if ((threadIdx.x & 31) == 0) sm[threadIdx.x >> 5] = v;
    __syncthreads();
    if (threadIdx.x == 0) {
        int s = 0;
#pragma unroll
        for (int j = 0; j < 8; j++) s += sm[j];
        g_bsum[side][blockIdx.x] = s;
    }
}
__global__ void scanB_k() {
    int side = blockIdx.x;
    __shared__ int sm[8];
    int v = g_bsum[side][threadIdx.x];
    int ex = block_exscan_256(v, sm);
    g_boff[side][threadIdx.x] = ex + v;
}
__global__ void scanC_k() {
    int side = blockIdx.y;
    int i = blockIdx.x * 256 + threadIdx.x;
    int d = g_degi[side][i];
    __shared__ int sm[8];
    int ex = block_exscan_256(d, sm);
    int off = (blockIdx.x ? g_boff[side][blockIdx.x - 1] : 0) + ex;
    g_row[side][i] = off;
    g_cursor[side][i] = off;
    if (i == NTOT - 1) g_row[side][NTOT] = NEDGE;
}

// ---------------- scatter edges into CSR order ----------------
__global__ void scatter_k(const int* __restrict__ ei0, const int* __restrict__ ei1) {
    int side = blockIdx.y;
    const int* ei = side ? ei1 : ei0;
    const int* src = ei;
    const int* dst = ei + NEDGE;
    int e = blockIdx.x * blockDim.x + threadIdx.x;
    if (e >= NEDGE) return;
    int s = src[e], d = dst[e];
    int pos = atomicAdd(&g_cursor[side][d], 1);
    g_esrc[side][pos] = s;
    g_enorm[side][pos] = g_dinv[side][s] * g_dinv[side][d];
}

// ---------------- gather-based aggregation (both sides via grid.y) --------
template <int OUT, bool BIAS, bool RELU>
__global__ void agg_k(const float* __restrict__ xw0, const float* __restrict__ xw1,
                      const float* __restrict__ bias,
                      float* __restrict__ out0, float* __restrict__ out1) {
    constexpr int C4 = OUT / 4;
    int side = blockIdx.y;
    const float* xw = side ? xw1 : xw0;
    float* out = side ? out1 : out0;
    int gid = blockIdx.x * blockDim.x + threadIdx.x;
    int node = gid / C4, chunk = gid % C4;
    if (node >= NTOT) return;
    const float4* xw4 = (const float4*)xw;
    float dv = g_dinv[side][node];
    float dv2 = dv * dv;
    float4 v = xw4[(size_t)node * C4 + chunk];
    float4 acc = make_float4(v.x * dv2, v.y * dv2, v.z * dv2, v.w * dv2);
    int beg = g_row[side][node], end = g_row[side][node + 1];
    for (int e = beg; e < end; e++) {
        int s = g_esrc[side][e];
        float nm = g_enorm[side][e];
        float4 u = xw4[(size_t)s * C4 + chunk];
        acc.x += u.x * nm; acc.y += u.y * nm; acc.z += u.z * nm; acc.w += u.w * nm;
    }
    if (BIAS) {
        acc.x += bias[chunk * 4 + 0];
        acc.y += bias[chunk * 4 + 1];
        acc.z += bias[chunk * 4 + 2];
        acc.w += bias[chunk * 4 + 3];
    }
    if (RELU) {
        acc.x = fmaxf(acc.x, 0.f); acc.y = fmaxf(acc.y, 0.f);
        acc.z = fmaxf(acc.z, 0.f); acc.w = fmaxf(acc.w, 0.f);
    }
    ((float4*)out)[(size_t)node * C4 + chunk] = acc;
}

// ---------------- 3xTF32 tensor-core GEMM (both sides via grid.y) ----------
template <int KIN, int NOUT, bool BIAS, bool RELU>
__global__ void gemm_mma_k(const float* __restrict__ x0, const float* __restrict__ x1,
                           const float* __restrict__ W, const float* __restrict__ bias,
                           float* __restrict__ out0, float* __restrict__ out1) {
    constexpr int KC = 16;
    constexpr int NT = NOUT / 8;
    constexpr int XS = KC + 4;
    constexpr int WS = NOUT + 8;
    __shared__ uint32_t Xh[128 * XS];
    __shared__ uint32_t Xl[128 * XS];
    __shared__ uint32_t Wh[KC * WS];
    __shared__ uint32_t Wl[KC * WS];
    int side = blockIdx.y;
    const float* x = side ? x1 : x0;
    float* out = side ? out1 : out0;
    int tid = threadIdx.x;
    int warp = tid >> 5, lane = tid & 31;
    size_t m0 = (size_t)blockIdx.x * 128;
    float acc[NT][4];
#pragma unroll
    for (int i = 0; i < NT; i++)
#pragma unroll
        for (int j = 0; j < 4; j++) acc[i][j] = 0.0f;

    for (int k0 = 0; k0 < KIN; k0 += KC) {
        for (int i = tid; i < 128 * (KC / 4); i += 256) {
            int r = i / (KC / 4), q = i % (KC / 4);
            float4 v = *(const float4*)&x[(m0 + r) * KIN + k0 + q * 4];
            uint32_t* ph = &Xh[r * XS + q * 4];
            uint32_t* pl = &Xl[r * XS + q * 4];
            split_tf32(v.x, ph[0], pl[0]); split_tf32(v.y, ph[1], pl[1]);
            split_tf32(v.z, ph[2], pl[2]); split_tf32(v.w, ph[3], pl[3]);
        }
        for (int i = tid; i < KC * NOUT / 4; i += 256) {
            int k = i / (NOUT / 4), q = i % (NOUT / 4);
            float4 v = *(const float4*)&W[(size_t)(k0 + k) * NOUT + q * 4];
            uint32_t* ph = &Wh[k * WS + q * 4];
            uint32_t* pl = &Wl[k * WS + q * 4];
            split_tf32(v.x, ph[0], pl[0]); split_tf32(v.y, ph[1], pl[1]);
            split_tf32(v.z, ph[2], pl[2]); split_tf32(v.w, ph[3], pl[3]);
        }
        __syncthreads();
#pragma unroll
        for (int ks = 0; ks < KC / 8; ks++) {
            uint32_t ah[4], al[4];
            int arow = warp * 16 + (lane >> 2);
            int acol = ks * 8 + (lane & 3);
            ah[0] = Xh[arow * XS + acol];       al[0] = Xl[arow * XS + acol];
            ah[1] = Xh[(arow + 8) * XS + acol]; al[1] = Xl[(arow + 8) * XS + acol];
            ah[2] = Xh[arow * XS + acol + 4];   al[2] = Xl[arow * XS + acol + 4];
            ah[3] = Xh[(arow + 8) * XS + acol + 4]; al[3] = Xl[(arow + 8) * XS + acol + 4];
            int bk = ks * 8 + (lane & 3);
            int bn0 = lane >> 2;
#pragma unroll
            for (int nt = 0; nt < NT; nt++) {
                uint32_t bh[2], bl[2];
                bh[0] = Wh[bk * WS + nt * 8 + bn0];
                bh[1] = Wh[(bk + 4) * WS + nt * 8 + bn0];
                bl[0] = Wl[bk * WS + nt * 8 + bn0];
                bl[1] = Wl[(bk + 4) * WS + nt * 8 + bn0];
                mma_tf32(acc[nt], ah, bh);
                mma_tf32(acc[nt], ah, bl);
                mma_tf32(acc[nt], al, bh);
            }
        }
        __syncthreads();
    }
    size_t row = m0 + warp * 16 + (lane >> 2);
    int col0 = (lane & 3) * 2;
#pragma unroll
    for (int nt = 0; nt < NT; nt++) {
        int c = nt * 8 + col0;
        float b0 = BIAS ? bias[c] : 0.0f, b1 = BIAS ? bias[c + 1] : 0.0f;
        float v0 = acc[nt][0] + b0, v1 = acc[nt][1] + b1;
        float v2 = acc[nt][2] + b0, v3 = acc[nt][3] + b1;
        if (RELU) {
            v0 = fmaxf(v0, 0.f); v1 = fmaxf(v1, 0.f);
            v2 = fmaxf(v2, 0.f); v3 = fmaxf(v3, 0.f);
        }
        *(float2*)&out[row * NOUT + c] = make_float2(v0, v1);
        *(float2*)&out[(row + 8) * NOUT + c] = make_float2(v2, v3);
    }
}

// ---------------- attention pooling (grid = (NB, 2)) ----------------
__global__ void pool_k(const float* __restrict__ Watt) {
    int side = blockIdx.y;
    int b = blockIdx.x;
    const float* fb = &g_feat[side][(size_t)b * NPG * D_F3];
    int t = threadIdx.x;  // 256
    __shared__ float p4[4][64];
    __shared__ float meanc[64];
    __shared__ float ctx[64];
    __shared__ float wsum[8][64];
    int d = t & 63, g = t >> 6;
    float loc = 0.0f;
    for (int r = g; r < NPG; r += 4) loc += fb[r * 64 + d];
    p4[g][d] = loc;
    __syncthreads();
    if (t < 64) meanc[t] = (p4[0][t] + p4[1][t] + p4[2][t] + p4[3][t]) * (1.0f / NPG);
    __syncthreads();
    if (t < 64) {
        float c = 0.0f;
        for (int i = 0; i < 64; i++) c += meanc[i] * Watt[i * 64 + t];
        ctx[t] = tanhf(c);
    }
    __syncthreads();
    int w = t >> 5, l = t & 31;
    float a0 = 0.0f, a1 = 0.0f;
    float c0 = ctx[l], c1 = ctx[l + 32];
    for (int r = w * 64; r < w * 64 + 64; r++) {
        float v0 = fb[r * 64 + l], v1 = fb[r * 64 + 32 + l];
        float dp = v0 * c0 + v1 * c1;
#pragma unroll
        for (int o = 16; o; o >>= 1) dp += __shfl_xor_sync(0xffffffffu, dp, o);
        float coef = sigmoidf_(dp);
        a0 += v0 * coef;
        a1 += v1 * coef;
    }
    wsum[w][l] = a0;
    wsum[w][l + 32] = a1;
    __syncthreads();
    if (t < 64) {
        float s = 0.0f;
        for (int w2 = 0; w2 < 8; w2++) s += wsum[w2][t];
        g_pool[side][b * 64 + t] = s;
    }
}

// ---------------- similarity via 3xTF32 mma, 128x128 tile, fp16 store ------
__global__ void sim_mma_k() {
    constexpr int KC = 16;
    constexpr int XS = KC + 4;
    int b = blockIdx.z;
    int i0 = blockIdx.y * 128, j0 = blockIdx.x * 128;
    __shared__ uint32_t Ah_s[128 * XS];
    __shared__ uint32_t Al_s[128 * XS];
    __shared__ uint32_t Bh_s[128 * XS];
    __shared__ uint32_t Bl_s[128 * XS];
    const float* f1 = &g_feat[0][(size_t)(b * NPG + i0) * 64];
    const float* f2 = &g_feat[1][(size_t)(b * NPG + j0) * 64];
    int tid = threadIdx.x;
    int warp = tid >> 5, lane = tid & 31;
    int wm = warp >> 2, wn = warp & 3;
    float acc[4][4][4];
#pragma unroll
    for (int mt = 0; mt < 4; mt++)
#pragma unroll
        for (int nt = 0; nt < 4; nt++)
#pragma unroll
            for (int j = 0; j < 4; j++) acc[mt][nt][j] = 0.0f;

    for (int k0 = 0; k0 < 64; k0 += KC) {
        for (int i = tid; i < 128 * (KC / 4); i += 256) {
            int r = i / (KC / 4), q = i % (KC / 4);
            float4 va = *(const float4*)&f1[r * 64 + k0 + q * 4];
            float4 vb = *(const float4*)&f2[r * 64 + k0 + q * 4];
            uint32_t* pah = &Ah_s[r * XS + q * 4];
            uint32_t* pal = &Al_s[r * XS + q * 4];
            uint32_t* pbh = &Bh_s[r * XS + q * 4];
            uint32_t* pbl = &Bl_s[r * XS + q * 4];
            split_tf32(va.x, pah[0], pal[0]); split_tf32(va.y, pah[1], pal[1]);
            split_tf32(va.z, pah[2], pal[2]); split_tf32(va.w, pah[3], pal[3]);
            split_tf32(vb.x, pbh[0], pbl[0]); split_tf32(vb.y, pbh[1], pbl[1]);
            split_tf32(vb.z, pbh[2], pbl[2]); split_tf32(vb.w, pbh[3], pbl[3]);
        }
        __syncthreads();
#pragma unroll
        for (int ks = 0; ks < KC / 8; ks++) {
            int acol = ks * 8 + (lane & 3);
            uint32_t ah[4][4], al[4][4], bh[4][2], bl[4][2];
#pragma unroll
            for (int mt = 0; mt < 4; mt++) {
                int arow = wm * 64 + mt * 16 + (lane >> 2);
                ah[mt][0] = Ah_s[arow * XS + acol];
                ah[mt][1] = Ah_s[(arow + 8) * XS + acol];
                ah[mt][2] = Ah_s[arow * XS + acol + 4];
                ah[mt][3] = Ah_s[(arow + 8) * XS + acol + 4];
                al[mt][0] = Al_s[arow * XS + acol];
                al[mt][1] = Al_s[(arow + 8) * XS + acol];
                al[mt][2] = Al_s[arow * XS + acol + 4];
                al[mt][3] = Al_s[(arow + 8) * XS + acol + 4];
            }
#pragma unroll
            for (int nt = 0; nt < 4; nt++) {
                int bnode = wn * 32 + nt * 8 + (lane >> 2);
                bh[nt][0] = Bh_s[bnode * XS + acol];
                bh[nt][1] = Bh_s[bnode * XS + acol + 4];
                bl[nt][0] = Bl_s[bnode * XS + acol];
                bl[nt][1] = Bl_s[bnode * XS + acol + 4];
            }
#pragma unroll
            for (int mt = 0; mt < 4; mt++)
#pragma unroll
                for (int nt = 0; nt < 4; nt++) {
                    mma_tf32(acc[mt][nt], ah[mt], bh[nt]);
                    mma_tf32(acc[mt][nt], ah[mt], bl[nt]);
                    mma_tf32(acc[mt][nt], al[mt], bh[nt]);
                }
        }
        __syncthreads();
    }
    float lmin = FLT_MAX, lmax = -FLT_MAX;
    __half* sp = &g_simh[(size_t)b * NPG * NPG];
    int col0 = (lane & 3) * 2;
#pragma unroll
    for (int mt = 0; mt < 4; mt++) {
        size_t r0 = (size_t)(i0 + wm * 64 + mt * 16 + (lane >> 2));
#pragma unroll
        for (int nt = 0; nt < 4; nt++) {
            int c = j0 + wn * 32 + nt * 8 + col0;
            float v0 = acc[mt][nt][0], v1 = acc[mt][nt][1];
            float v2 = acc[mt][nt][2], v3 = acc[mt][nt][3];
            lmin = fminf(lmin, fminf(fminf(v0, v1), fminf(v2, v3)));
            lmax = fmaxf(lmax, fmaxf(fmaxf(v0, v1), fmaxf(v2, v3)));
            *(__half2*)&sp[r0 * NPG + c] = __floats2half2_rn(v0, v1);
            *(__half2*)&sp[(r0 + 8) * NPG + c] = __floats2half2_rn(v2, v3);
        }
    }
    __shared__ float rmin[256], rmax[256];
    rmin[tid] = lmin;
    rmax[tid] = lmax;
    __syncthreads();
    for (int s = 128; s > 0; s >>= 1) {
        if (tid < s) {
            rmin[tid] = fminf(rmin[tid], rmin[tid + s]);
            rmax[tid] = fmaxf(rmax[tid], rmax[tid + s]);
        }
        __syncthreads();
    }
    if (tid == 0) {
        atomicMinFloat(&g_smin[b], rmin[0]);
        atomicMaxFloat(&g_smax[b], rmax[0]);
    }
}

// ---------------- histogram via threshold CDF, per-lane counters -----------
// grid (8, NB), 256 threads. Thresholds are inverted once per block
// (thr_k = logit(vmin + k*width)); each lane keeps 15 private CDF counters
// incremented by predicated compares — no MUFU, no atomics in the hot loop.
__global__ void hist_k() {
    int b = blockIdx.y;
    int part = blockIdx.x;               // 8 parts per graph
    int t = threadIdx.x;
    int lane = t & 31, warp = t >> 5;    // 8 warps
    __shared__ float thr_s[15];
    if (t < 15) {
        float vmin = sigmoidf_(g_smin[b]);
        float vmax = sigmoidf_(g_smax[b]);
        float width = (vmax - vmin) * (1.0f / D_BINS);
        if (width > 0.0f) {
            float bnd = vmin + (float)(t + 1) * width;
            thr_s[t] = logf(bnd / (1.0f - bnd));
        } else {
            thr_s[t] = FLT_MAX;
        }
    }
    __syncthreads();
    float T[15];
#pragma unroll
    for (int k = 0; k < 15; k++) T[k] = thr_s[k];

    // this block handles 4096 contiguous uint4 (32768 halfs)
    const uint4* qp = (const uint4*)&g_simh[(size_t)b * NPG * NPG] + part * 4096;
    int C[15];
#pragma unroll
    for (int k = 0; k < 15; k++) C[k] = 0;
    for (int i = t; i < 4096; i += 256) {
        uint4 q = qp[i];
        float2 p0 = __half22float2(*(__half2*)&q.x);
        float2 p1 = __half22float2(*(__half2*)&q.y);
        float2 p2 = __half22float2(*(__half2*)&q.z);
        float2 p3 = __half22float2(*(__half2*)&q.w);
        float v[8] = {p0.x, p0.y, p1.x, p1.y, p2.x, p2.y, p3.x, p3.y};
#pragma unroll
        for (int k = 0; k < 15; k++) {
#pragma unroll
            for (int j = 0; j < 8; j++) C[k] += (v[j] >= T[k]) ? 1 : 0;
        }
    }
    // warp reduce each counter, then block reduce via shared
    __shared__ int red[8][15];
#pragma unroll
    for (int k = 0; k < 15; k++) {
        int c = C[k];
#pragma unroll
        for (int o = 16; o; o >>= 1) c += __shfl_xor_sync(0xffffffffu, c, o);
        if (lane == 0) red[warp][k] = c;
    }
    __syncthreads();
    if (t < 15) {
        int s = 0;
#pragma unroll
        for (int w = 0; w < 8; w++) s += red[w][t];
        atomicAdd(&g_cdf[b][t], s);
    }
}

// ---------------- final head (one block per graph, 128 threads) ----------
__global__ void final_k(const float* __restrict__ Wt, const float* __restrict__ Wtb,
                        const float* __restrict__ tb, const float* __restrict__ W1,
                        const float* __restrict__ b1, const float* __restrict__ Ws,
                        const float* __restrict__ bs, float* __restrict__ out) {
    int b = blockIdx.x, t = threadIdx.x;
    __shared__ float p1s[64], p2s[64];
    __shared__ float scp[64 * 16];
    __shared__ float feat[32];
    __shared__ float hs[32];
    if (t < 64) {
        p1s[t] = g_pool[0][b * 64 + t];
        p2s[t] = g_pool[1][b * 64 + t];
    }
    __syncthreads();
    if (t < 64) {
        float s[16];
#pragma unroll
        for (int k = 0; k < 16; k++) s[k] = 0.0f;
        for (int j = 0; j < 64; j++) {
            float pj = p2s[j];
            const float* wp = &Wt[(size_t)(t * 64 + j) * 16];
#pragma unroll
            for (int k = 0; k < 16; k++) s[k] += wp[k] * pj;
        }
        float p1v = p1s[t];
#pragma unroll
        for (int k = 0; k < 16; k++) scp[t * 16 + k] = p1v * s[k];
    }
    __syncthreads();
    if (t < 16) {
        float acc = tb[t];
        for (int i = 0; i < 64; i++) acc += scp[i * 16 + t];
        float blk = 0.0f;
        for (int i = 0; i < 64; i++) blk += Wtb[t * 128 + i] * p1s[i];
        for (int i = 0; i < 64; i++) blk += Wtb[t * 128 + 64 + i] * p2s[i];
        float tv = acc + blk;
        feat[t] = fmaxf(tv, 0.0f);
        // histogram bin t from CDF differences
        int C_lo = (t == 0) ? NPG * NPG : g_cdf[b][t - 1];
        int C_hi = (t == 15) ? 0 : g_cdf[b][t];
        feat[16 + t] = (float)(C_lo - C_hi) * (1.0f / ((float)NPG * (float)NPG));
    }
    __syncthreads();
    if (t < 32) {
        float acc = b1[t];
        for (int i = 0; i < 32; i++) acc += feat[i] * W1[i * 32 + t];
        hs[t] = fmaxf(acc, 0.0f);
    }
    __syncthreads();
    if (t == 0) {
        float acc = bs[0];
        for (int j = 0; j < 32; j++) acc += hs[j] * Ws[j];
        out[b] = sigmoidf_(acc);
    }
}

// ---------------- launcher ----------------
extern "C" void kernel_launch(void* const* d_in, const int* in_sizes, int n_in,
                              void* d_out, int out_size) {
    const float* x1  = (const float*)d_in[0];
    const float* x2  = (const float*)d_in[1];
    const int* ei1   = (const int*)d_in[2];
    const int* ei2   = (const int*)d_in[3];
    const float* Wc1 = (const float*)d_in[6];
    const float* bc1 = (const float*)d_in[7];
    const float* Wc2 = (const float*)d_in[8];
    const float* bc2 = (const float*)d_in[9];
    const float* Wc3 = (const float*)d_in[10];
    const float* bc3 = (const float*)d_in[11];
    const float* Watt = (const float*)d_in[12];
    const float* Wt  = (const float*)d_in[13];
    const float* Wtb = (const float*)d_in[14];
    const float* tb  = (const float*)d_in[15];
    const float* W1  = (const float*)d_in[16];
    const float* b1  = (const float*)d_in[17];
    const float* Ws  = (const float*)d_in[18];
    const float* bs  = (const float*)d_in[19];
    float* out = (float*)d_out;

    void* p;
    float *a0, *a1, *b0, *b1p, *f0, *f1;
    cudaGetSymbolAddress(&p, g_bufA);
    a0 = (float*)p; a1 = a0 + (size_t)NTOT * D_F1;
    cudaGetSymbolAddress(&p, g_bufB);
    b0 = (float*)p; b1p = b0 + (size_t)NTOT * D_F1;
    cudaGetSymbolAddress(&p, g_feat);
    f0 = (float*)p; f1 = f0 + (size_t)NTOT * D_F3;

    init_k<<<NTOT / 256, 256>>>();

    // CSR build for BOTH sides (batched over grid.y)
    deg_k<<<dim3(NEDGE / 256, 2), 256>>>(ei1 + NEDGE, ei2 + NEDGE);
    scanA_k<<<dim3(256, 2), 256>>>();   // also computes dinv
    scanB_k<<<2, 256>>>();
    scanC_k<<<dim3(256, 2), 256>>>();
    scatter_k<<<dim3(NEDGE / 256, 2), 256>>>(ei1, ei2);

    // conv pipeline, both sides per launch
    agg_k<32, false, false><<<dim3(NTOT * 8 / 256, 2), 256>>>(x1, x2, nullptr, a0, a1);
    gemm_mma_k<32, 128, true, true><<<dim3(NTOT / 128, 2), 256>>>(a0, a1, Wc1, bc1, b0, b1p);

    gemm_mma_k<128, 96, false, false><<<dim3(NTOT / 128, 2), 256>>>(b0, b1p, Wc2, nullptr, a0, a1);
    agg_k<96, true, true><<<dim3(NTOT * 24 / 256, 2), 256>>>(a0, a1, bc2, b0, b1p);

    gemm_mma_k<96, 64, false, false><<<dim3(NTOT / 128, 2), 256>>>(b0, b1p, Wc3, nullptr, a0, a1);
    agg_k<64, true, false><<<dim3(NTOT * 16 / 256, 2), 256>>>(a0, a1, bc3, f0, f1);

    pool_k<<<dim3(NB, 2), 256>>>(Watt);

    sim_mma_k<<<dim3(4, 4, NB), 256>>>();
    hist_k<<<dim3(8, NB), 256>>>();
    final_k<<<NB, 128>>>(Wt, Wtb, tb, W1, b1, Ws, bs, out);
}

// round 10
// speedup vs baseline: 1.3319x; 1.1651x over previous
#include <cuda_runtime.h>
#include <cuda_fp16.h>
#include <math.h>
#include <cfloat>
#include <stdint.h>

// ---------------- problem dims (fixed) ----------------
#define NTOT  65536      // nodes per side (B*N)
#define NEDGE 524288     // edges per side
#define NB    128        // graphs
#define NPG   512        // nodes per graph
#define D_F1  128
#define D_F2  96
#define D_F3  64
#define D_BINS 16

// ---------------- device scratch (per-side slabs for batched launches) -----
__device__ float g_bufA[2][NTOT * D_F1];
__device__ float g_bufB[2][NTOT * D_F1];
__device__ float g_feat[2][NTOT * D_F3];
__device__ float g_dinv[2][NTOT];
__device__ int   g_degi[2][NTOT];
__device__ int   g_row[2][NTOT + 1];
__device__ int   g_cursor[2][NTOT];
__device__ int   g_bsum[2][256];
__device__ int   g_boff[2][256];
__device__ int   g_esrc[2][NEDGE];
__device__ float g_enorm[2][NEDGE];
__device__ __half g_simh[(size_t)NB * NPG * NPG];   // fp16 similarity scores
__device__ int   g_cdf[NB][15];                      // C[k] = #{s >= thr_{k+1}}
__device__ float g_smin[NB];
__device__ float g_smax[NB];
__device__ float g_pool[2][NB * D_F3];

__device__ __forceinline__ float sigmoidf_(float x) { return 1.0f / (1.0f + expf(-x)); }

__device__ __forceinline__ void atomicMinFloat(float* addr, float val) {
    int old = __float_as_int(*addr);
    while (__int_as_float(old) > val) {
        int assumed = old;
        old = atomicCAS((int*)addr, assumed, __float_as_int(val));
        if (old == assumed) break;
    }
}
__device__ __forceinline__ void atomicMaxFloat(float* addr, float val) {
    int old = __float_as_int(*addr);
    while (__int_as_float(old) < val) {
        int assumed = old;
        old = atomicCAS((int*)addr, assumed, __float_as_int(val));
        if (old == assumed) break;
    }
}

// ---------------- bf16x3 helpers (fp32 emulation via bf16 split) -----------
// pack bf16(x0),bf16(x1) into h (x0 in low half), residuals into l
__device__ __forceinline__ void split2(float x0, float x1, uint32_t& h, uint32_t& l) {
    asm("cvt.rn.bf16x2.f32 %0, %1, %2;" : "=r"(h) : "f"(x1), "f"(x0));
    float r0 = x0 - __uint_as_float(h << 16);
    float r1 = x1 - __uint_as_float(h & 0xffff0000u);
    asm("cvt.rn.bf16x2.f32 %0, %1, %2;" : "=r"(l) : "f"(r1), "f"(r0));
}
// D(16x8) += A(16x16,row) * B(16x8,col)   bf16 in, f32 accum
__device__ __forceinline__ void mma_bf16(float* d, const uint32_t* a, const uint32_t* b) {
    asm volatile(
        "mma.sync.aligned.m16n8k16.row.col.f32.bf16.bf16.f32 "
        "{%0,%1,%2,%3}, {%4,%5,%6,%7}, {%8,%9}, {%0,%1,%2,%3};\n"
        : "+f"(d[0]), "+f"(d[1]), "+f"(d[2]), "+f"(d[3])
        : "r"(a[0]), "r"(a[1]), "r"(a[2]), "r"(a[3]), "r"(b[0]), "r"(b[1]));
}

// block-wide exclusive scan of 256 ints (one value per thread)
__device__ __forceinline__ int block_exscan_256(int v, int* sm8) {
    int lane = threadIdx.x & 31, w = threadIdx.x >> 5;
    int x = v;
#pragma unroll
    for (int o = 1; o < 32; o <<= 1) {
        int y = __shfl_up_sync(0xffffffffu, x, o);
        if (lane >= o) x += y;
    }
    if (lane == 31) sm8[w] = x;
    __syncthreads();
    if (threadIdx.x < 8) {
        int s = sm8[threadIdx.x];
#pragma unroll
        for (int o = 1; o < 8; o <<= 1) {
            int y = __shfl_up_sync(0xffu, s, o);
            if ((int)threadIdx.x >= o) s += y;
        }
        sm8[threadIdx.x] = s;
    }
    __syncthreads();
    int woff = w ? sm8[w - 1] : 0;
    return woff + x - v;
}

// ---------------- init ----------------
__global__ void init_k() {
    int i = blockIdx.x * blockDim.x + threadIdx.x;
    if (i < NTOT) { g_degi[0][i] = 0; g_degi[1][i] = 0; }
    if (i < NB * 15) g_cdf[i / 15][i % 15] = 0;
    if (i < NB) { g_smin[i] = FLT_MAX; g_smax[i] = -FLT_MAX; }
}

// ---------------- degree (both sides via grid.y) ----------------
__global__ void deg_k(const int* __restrict__ dst0, const int* __restrict__ dst1) {
    int side = blockIdx.y;
    const int* dst = side ? dst1 : dst0;
    int e = blockIdx.x * blockDim.x + threadIdx.x;
    if (e < NEDGE) atomicAdd(&g_degi[side][dst[e]], 1);
}

// ---------------- 3-phase parallel scan (A also computes dinv) -------------
__global__ void scanA_k() {
    int side = blockIdx.y;
    int i = blockIdx.x * 256 + threadIdx.x;
    int v = g_degi[side][i];
    g_dinv[side][i] = rsqrtf((float)v + 1.0f);
#pragma unroll
    for (int o = 16; o; o >>= 1) v += __shfl_xor_sync(0xffffffffu, v, o);
    __shared__ int sm[8];
    if ((threadIdx.x & 31) == 0) sm[threadIdx.x >> 5] = v;
    __syncthreads();
    if (threadIdx.x == 0) {
        int s = 0;
#pragma unroll
        for (int j = 0; j < 8; j++) s += sm[j];
        g_bsum[side][blockIdx.x] = s;
    }
}
__global__ void scanB_k() {
    int side = blockIdx.x;
    __shared__ int sm[8];
    int v = g_bsum[side][threadIdx.x];
    int ex = block_exscan_256(v, sm);
    g_boff[side][threadIdx.x] = ex + v;
}
__global__ void scanC_k() {
    int side = blockIdx.y;
    int i = blockIdx.x * 256 + threadIdx.x;
    int d = g_degi[side][i];
    __shared__ int sm[8];
    int ex = block_exscan_256(d, sm);
    int off = (blockIdx.x ? g_boff[side][blockIdx.x - 1] : 0) + ex;
    g_row[side][i] = off;
    g_cursor[side][i] = off;
    if (i == NTOT - 1) g_row[side][NTOT] = NEDGE;
}

// ---------------- scatter edges into CSR order ----------------
__global__ void scatter_k(const int* __restrict__ ei0, const int* __restrict__ ei1) {
    int side = blockIdx.y;
    const int* ei = side ? ei1 : ei0;
    const int* src = ei;
    const int* dst = ei + NEDGE;
    int e = blockIdx.x * blockDim.x + threadIdx.x;
    if (e >= NEDGE) return;
    int s = src[e], d = dst[e];
    int pos = atomicAdd(&g_cursor[side][d], 1);
    g_esrc[side][pos] = s;
    g_enorm[side][pos] = g_dinv[side][s] * g_dinv[side][d];
}

// ---------------- gather-based aggregation (both sides via grid.y) --------
template <int OUT, bool BIAS, bool RELU>
__global__ void agg_k(const float* __restrict__ xw0, const float* __restrict__ xw1,
                      const float* __restrict__ bias,
                      float* __restrict__ out0, float* __restrict__ out1) {
    constexpr int C4 = OUT / 4;
    int side = blockIdx.y;
    const float* xw = side ? xw1 : xw0;
    float* out = side ? out1 : out0;
    int gid = blockIdx.x * blockDim.x + threadIdx.x;
    int node = gid / C4, chunk = gid % C4;
    if (node >= NTOT) return;
    const float4* xw4 = (const float4*)xw;
    float dv = g_dinv[side][node];
    float dv2 = dv * dv;
    float4 v = xw4[(size_t)node * C4 + chunk];
    float4 acc = make_float4(v.x * dv2, v.y * dv2, v.z * dv2, v.w * dv2);
    int beg = g_row[side][node], end = g_row[side][node + 1];
    for (int e = beg; e < end; e++) {
        int s = g_esrc[side][e];
        float nm = g_enorm[side][e];
        float4 u = xw4[(size_t)s * C4 + chunk];
        acc.x += u.x * nm; acc.y += u.y * nm; acc.z += u.z * nm; acc.w += u.w * nm;
    }
    if (BIAS) {
        acc.x += bias[chunk * 4 + 0];
        acc.y += bias[chunk * 4 + 1];
        acc.z += bias[chunk * 4 + 2];
        acc.w += bias[chunk * 4 + 3];
    }
    if (RELU) {
        acc.x = fmaxf(acc.x, 0.f); acc.y = fmaxf(acc.y, 0.f);
        acc.z = fmaxf(acc.z, 0.f); acc.w = fmaxf(acc.w, 0.f);
    }
    ((float4*)out)[(size_t)node * C4 + chunk] = acc;
}

// ---------------- bf16x3 tensor-core GEMM (both sides via grid.y) ----------
// block 256 thr = 8 warps; block M-tile 128, warp w -> rows [w*16, w*16+16).
// X tiles [row][k-pair] (pitch XS=20, conflict-free frag loads); W tile [n][kp].
template <int KIN, int NOUT, bool BIAS, bool RELU>
__global__ void gemm_mma_k(const float* __restrict__ x0, const float* __restrict__ x1,
                           const float* __restrict__ W, const float* __restrict__ bias,
                           float* __restrict__ out0, float* __restrict__ out1) {
    constexpr int KC = 32;            // k elements per chunk
    constexpr int KP = KC / 2;        // 16 half2 per row
    constexpr int NT = NOUT / 8;
    constexpr int XS = 20;
    constexpr int WS = 20;
    __shared__ uint32_t Xh[128 * XS];
    __shared__ uint32_t Xl[128 * XS];
    __shared__ uint32_t Wh[NOUT * WS];
    __shared__ uint32_t Wl[NOUT * WS];
    int side = blockIdx.y;
    const float* x = side ? x1 : x0;
    float* out = side ? out1 : out0;
    int tid = threadIdx.x;
    int warp = tid >> 5, lane = tid & 31;
    size_t m0 = (size_t)blockIdx.x * 128;
    float acc[NT][4];
#pragma unroll
    for (int i = 0; i < NT; i++)
#pragma unroll
        for (int j = 0; j < 4; j++) acc[i][j] = 0.0f;

    for (int k0 = 0; k0 < KIN; k0 += KC) {
        // X tile: 128 rows x 8 float4 -> [r][q*2], [r][q*2+1]
        for (int i = tid; i < 128 * 8; i += 256) {
            int r = i >> 3, q = i & 7;
            float4 v = *(const float4*)&x[(m0 + r) * KIN + k0 + q * 4];
            uint32_t h0, l0, h1, l1;
            split2(v.x, v.y, h0, l0);
            split2(v.z, v.w, h1, l1);
            Xh[r * XS + q * 2] = h0;     Xh[r * XS + q * 2 + 1] = h1;
            Xl[r * XS + q * 2] = l0;     Xl[r * XS + q * 2 + 1] = l1;
        }
        // W tile: [n][kp] from row-major W[k][n]
        for (int i = tid; i < NOUT * KP; i += 256) {
            int kp = i / NOUT, n = i % NOUT;
            float w0 = W[(size_t)(k0 + 2 * kp) * NOUT + n];
            float w1 = W[(size_t)(k0 + 2 * kp + 1) * NOUT + n];
            uint32_t h, l;
            split2(w0, w1, h, l);
            Wh[n * WS + kp] = h;
            Wl[n * WS + kp] = l;
        }
        __syncthreads();
#pragma unroll
        for (int s = 0; s < 2; s++) {       // two k16 steps per KC=32
            int kb = s * 8 + (lane & 3);
            uint32_t ah[4], al[4];
            int arow = warp * 16 + (lane >> 2);
            ah[0] = Xh[arow * XS + kb];           al[0] = Xl[arow * XS + kb];
            ah[1] = Xh[(arow + 8) * XS + kb];     al[1] = Xl[(arow + 8) * XS + kb];
            ah[2] = Xh[arow * XS + kb + 4];       al[2] = Xl[arow * XS + kb + 4];
            ah[3] = Xh[(arow + 8) * XS + kb + 4]; al[3] = Xl[(arow + 8) * XS + kb + 4];
            int bn = lane >> 2;
#pragma unroll
            for (int nt = 0; nt < NT; nt++) {
                uint32_t bh[2], bl[2];
                int nb = (nt * 8 + bn) * WS;
                bh[0] = Wh[nb + kb]; bh[1] = Wh[nb + kb + 4];
                bl[0] = Wl[nb + kb]; bl[1] = Wl[nb + kb + 4];
                mma_bf16(acc[nt], ah, bh);
                mma_bf16(acc[nt], ah, bl);
                mma_bf16(acc[nt], al, bh);
            }
        }
        __syncthreads();
    }
    size_t row = m0 + warp * 16 + (lane >> 2);
    int col0 = (lane & 3) * 2;
#pragma unroll
    for (int nt = 0; nt < NT; nt++) {
        int c = nt * 8 + col0;
        float b0 = BIAS ? bias[c] : 0.0f, b1 = BIAS ? bias[c + 1] : 0.0f;
        float v0 = acc[nt][0] + b0, v1 = acc[nt][1] + b1;
        float v2 = acc[nt][2] + b0, v3 = acc[nt][3] + b1;
        if (RELU) {
            v0 = fmaxf(v0, 0.f); v1 = fmaxf(v1, 0.f);
            v2 = fmaxf(v2, 0.f); v3 = fmaxf(v3, 0.f);
        }
        *(float2*)&out[row * NOUT + c] = make_float2(v0, v1);
        *(float2*)&out[(row + 8) * NOUT + c] = make_float2(v2, v3);
    }
}

// ---------------- attention pooling (grid = (NB, 2)) ----------------
__global__ void pool_k(const float* __restrict__ Watt) {
    int side = blockIdx.y;
    int b = blockIdx.x;
    const float* fb = &g_feat[side][(size_t)b * NPG * D_F3];
    int t = threadIdx.x;  // 256
    __shared__ float p4[4][64];
    __shared__ float meanc[64];
    __shared__ float ctx[64];
    __shared__ float wsum[8][64];
    int d = t & 63, g = t >> 6;
    float loc = 0.0f;
    for (int r = g; r < NPG; r += 4) loc += fb[r * 64 + d];
    p4[g][d] = loc;
    __syncthreads();
    if (t < 64) meanc[t] = (p4[0][t] + p4[1][t] + p4[2][t] + p4[3][t]) * (1.0f / NPG);
    __syncthreads();
    if (t < 64) {
        float c = 0.0f;
        for (int i = 0; i < 64; i++) c += meanc[i] * Watt[i * 64 + t];
        ctx[t] = tanhf(c);
    }
    __syncthreads();
    int w = t >> 5, l = t & 31;
    float a0 = 0.0f, a1 = 0.0f;
    float c0 = ctx[l], c1 = ctx[l + 32];
    for (int r = w * 64; r < w * 64 + 64; r++) {
        float v0 = fb[r * 64 + l], v1 = fb[r * 64 + 32 + l];
        float dp = v0 * c0 + v1 * c1;
#pragma unroll
        for (int o = 16; o; o >>= 1) dp += __shfl_xor_sync(0xffffffffu, dp, o);
        float coef = sigmoidf_(dp);
        a0 += v0 * coef;
        a1 += v1 * coef;
    }
    wsum[w][l] = a0;
    wsum[w][l + 32] = a1;
    __syncthreads();
    if (t < 64) {
        float s = 0.0f;
        for (int w2 = 0; w2 < 8; w2++) s += wsum[w2][t];
        g_pool[side][b * 64 + t] = s;
    }
}

// ---------------- similarity via bf16x3 mma, 128x128 tile, fp16 store ------
__global__ void sim_mma_k() {
    constexpr int XS = 20;
    int b = blockIdx.z;
    int i0 = blockIdx.y * 128, j0 = blockIdx.x * 128;
    __shared__ uint32_t Ah_s[128 * XS];
    __shared__ uint32_t Al_s[128 * XS];
    __shared__ uint32_t Bh_s[128 * XS];
    __shared__ uint32_t Bl_s[128 * XS];
    const float* f1 = &g_feat[0][(size_t)(b * NPG + i0) * 64];
    const float* f2 = &g_feat[1][(size_t)(b * NPG + j0) * 64];
    int tid = threadIdx.x;
    int warp = tid >> 5, lane = tid & 31;
    int wm = warp >> 2, wn = warp & 3;
    float acc[4][4][4];
#pragma unroll
    for (int mt = 0; mt < 4; mt++)
#pragma unroll
        for (int nt = 0; nt < 4; nt++)
#pragma unroll
            for (int j = 0; j < 4; j++) acc[mt][nt][j] = 0.0f;

    for (int k0 = 0; k0 < 64; k0 += 32) {
        for (int i = tid; i < 128 * 8; i += 256) {
            int r = i >> 3, q = i & 7;
            float4 va = *(const float4*)&f1[r * 64 + k0 + q * 4];
            float4 vb = *(const float4*)&f2[r * 64 + k0 + q * 4];
            uint32_t h0, l0, h1, l1;
            split2(va.x, va.y, h0, l0);
            split2(va.z, va.w, h1, l1);
            Ah_s[r * XS + q * 2] = h0;     Ah_s[r * XS + q * 2 + 1] = h1;
            Al_s[r * XS + q * 2] = l0;     Al_s[r * XS + q * 2 + 1] = l1;
            split2(vb.x, vb.y, h0, l0);
            split2(vb.z, vb.w, h1, l1);
            Bh_s[r * XS + q * 2] = h0;     Bh_s[r * XS + q * 2 + 1] = h1;
            Bl_s[r * XS + q * 2] = l0;     Bl_s[r * XS + q * 2 + 1] = l1;
        }
        __syncthreads();
#pragma unroll
        for (int s = 0; s < 2; s++) {
            int kb = s * 8 + (lane & 3);
            uint32_t ah[4][4], al[4][4], bh[4][2], bl[4][2];
#pragma unroll
            for (int mt = 0; mt < 4; mt++) {
                int arow = wm * 64 + mt * 16 + (lane >> 2);
                ah[mt][0] = Ah_s[arow * XS + kb];
                ah[mt][1] = Ah_s[(arow + 8) * XS + kb];
                ah[mt][2] = Ah_s[arow * XS + kb + 4];
                ah[mt][3] = Ah_s[(arow + 8) * XS + kb + 4];
                al[mt][0] = Al_s[arow * XS + kb];
                al[mt][1] = Al_s[(arow + 8) * XS + kb];
                al[mt][2] = Al_s[arow * XS + kb + 4];
                al[mt][3] = Al_s[(arow + 8) * XS + kb + 4];
            }
#pragma unroll
            for (int nt = 0; nt < 4; nt++) {
                int bnode = wn * 32 + nt * 8 + (lane >> 2);
                bh[nt][0] = Bh_s[bnode * XS + kb];
                bh[nt][1] = Bh_s[bnode * XS + kb + 4];
                bl[nt][0] = Bl_s[bnode * XS + kb];
                bl[nt][1] = Bl_s[bnode * XS + kb + 4];
            }
#pragma unroll
            for (int mt = 0; mt < 4; mt++)
#pragma unroll
                for (int nt = 0; nt < 4; nt++) {
                    mma_bf16(acc[mt][nt], ah[mt], bh[nt]);
                    mma_bf16(acc[mt][nt], ah[mt], bl[nt]);
                    mma_bf16(acc[mt][nt], al[mt], bh[nt]);
                }
        }
        __syncthreads();
    }
    float lmin = FLT_MAX, lmax = -FLT_MAX;
    __half* sp = &g_simh[(size_t)b * NPG * NPG];
    int col0 = (lane & 3) * 2;
#pragma unroll
    for (int mt = 0; mt < 4; mt++) {
        size_t r0 = (size_t)(i0 + wm * 64 + mt * 16 + (lane >> 2));
#pragma unroll
        for (int nt = 0; nt < 4; nt++) {
            int c = j0 + wn * 32 + nt * 8 + col0;
            float v0 = acc[mt][nt][0], v1 = acc[mt][nt][1];
            float v2 = acc[mt][nt][2], v3 = acc[mt][nt][3];
            lmin = fminf(lmin, fminf(fminf(v0, v1), fminf(v2, v3)));
            lmax = fmaxf(lmax, fmaxf(fmaxf(v0, v1), fmaxf(v2, v3)));
            *(__half2*)&sp[r0 * NPG + c] = __floats2half2_rn(v0, v1);
            *(__half2*)&sp[(r0 + 8) * NPG + c] = __floats2half2_rn(v2, v3);
        }
    }
    __shared__ float rmin[256], rmax[256];
    rmin[tid] = lmin;
    rmax[tid] = lmax;
    __syncthreads();
    for (int s = 128; s > 0; s >>= 1) {
        if (tid < s) {
            rmin[tid] = fminf(rmin[tid], rmin[tid + s]);
            rmax[tid] = fmaxf(rmax[tid], rmax[tid + s]);
        }
        __syncthreads();
    }
    if (tid == 0) {
        atomicMinFloat(&g_smin[b], rmin[0]);
        atomicMaxFloat(&g_smax[b], rmax[0]);
    }
}

// ---------------- histogram via threshold CDF, per-lane counters -----------
__global__ void hist_k() {
    int b = blockIdx.y;
    int part = blockIdx.x;               // 8 parts per graph
    int t = threadIdx.x;
    int lane = t & 31, warp = t >> 5;    // 8 warps
    __shared__ float thr_s[15];
    if (t < 15) {
        float vmin = sigmoidf_(g_smin[b]);
        float vmax = sigmoidf_(g_smax[b]);
        float width = (vmax - vmin) * (1.0f / D_BINS);
        if (width > 0.0f) {
            float bnd = vmin + (float)(t + 1) * width;
            thr_s[t] = logf(bnd / (1.0f - bnd));
        } else {
            thr_s[t] = FLT_MAX;
        }
    }
    __syncthreads();
    float T[15];
#pragma unroll
    for (int k = 0; k < 15; k++) T[k] = thr_s[k];

    const uint4* qp = (const uint4*)&g_simh[(size_t)b * NPG * NPG] + part * 4096;
    int C[15];
#pragma unroll
    for (int k = 0; k < 15; k++) C[k] = 0;
    for (int i = t; i < 4096; i += 256) {
        uint4 q = qp[i];
        float2 p0 = __half22float2(*(__half2*)&q.x);
        float2 p1 = __half22float2(*(__half2*)&q.y);
        float2 p2 = __half22float2(*(__half2*)&q.z);
        float2 p3 = __half22float2(*(__half2*)&q.w);
        float v[8] = {p0.x, p0.y, p1.x, p1.y, p2.x, p2.y, p3.x, p3.y};
#pragma unroll
        for (int k = 0; k < 15; k++) {
#pragma unroll
            for (int j = 0; j < 8; j++) C[k] += (v[j] >= T[k]) ? 1 : 0;
        }
    }
    __shared__ int red[8][15];
#pragma unroll
    for (int k = 0; k < 15; k++) {
        int c = C[k];
#pragma unroll
        for (int o = 16; o; o >>= 1) c += __shfl_xor_sync(0xffffffffu, c, o);
        if (lane == 0) red[warp][k] = c;
    }
    __syncthreads();
    if (t < 15) {
        int s = 0;
#pragma unroll
        for (int w = 0; w < 8; w++) s += red[w][t];
        atomicAdd(&g_cdf[b][t], s);
    }
}

// ---------------- final head (one block per graph, 128 threads) ----------
__global__ void final_k(const float* __restrict__ Wt, const float* __restrict__ Wtb,
                        const float* __restrict__ tb, const float* __restrict__ W1,
                        const float* __restrict__ b1, const float* __restrict__ Ws,
                        const float* __restrict__ bs, float* __restrict__ out) {
    int b = blockIdx.x, t = threadIdx.x;
    __shared__ float p1s[64], p2s[64];
    __shared__ float scp[64 * 16];
    __shared__ float feat[32];
    __shared__ float hs[32];
    if (t < 64) {
        p1s[t] = g_pool[0][b * 64 + t];
        p2s[t] = g_pool[1][b * 64 + t];
    }
    __syncthreads();
    if (t < 64) {
        float s[16];
#pragma unroll
        for (int k = 0; k < 16; k++) s[k] = 0.0f;
        for (int j = 0; j < 64; j++) {
            float pj = p2s[j];
            const float* wp = &Wt[(size_t)(t * 64 + j) * 16];
#pragma unroll
            for (int k = 0; k < 16; k++) s[k] += wp[k] * pj;
        }
        float p1v = p1s[t];
#pragma unroll
        for (int k = 0; k < 16; k++) scp[t * 16 + k] = p1v * s[k];
    }
    __syncthreads();
    if (t < 16) {
        float acc = tb[t];
        for (int i = 0; i < 64; i++) acc += scp[i * 16 + t];
        float blk = 0.0f;
        for (int i = 0; i < 64; i++) blk += Wtb[t * 128 + i] * p1s[i];
        for (int i = 0; i < 64; i++) blk += Wtb[t * 128 + 64 + i] * p2s[i];
        float tv = acc + blk;
        feat[t] = fmaxf(tv, 0.0f);
        int C_lo = (t == 0) ? NPG * NPG : g_cdf[b][t - 1];
        int C_hi = (t == 15) ? 0 : g_cdf[b][t];
        feat[16 + t] = (float)(C_lo - C_hi) * (1.0f / ((float)NPG * (float)NPG));
    }
    __syncthreads();
    if (t < 32) {
        float acc = b1[t];
        for (int i = 0; i < 32; i++) acc += feat[i] * W1[i * 32 + t];
        hs[t] = fmaxf(acc, 0.0f);
    }
    __syncthreads();
    if (t == 0) {
        float acc = bs[0];
        for (int j = 0; j < 32; j++) acc += hs[j] * Ws[j];
        out[b] = sigmoidf_(acc);
    }
}

// ---------------- launcher ----------------
extern "C" void kernel_launch(void* const* d_in, const int* in_sizes, int n_in,
                              void* d_out, int out_size) {
    const float* x1  = (const float*)d_in[0];
    const float* x2  = (const float*)d_in[1];
    const int* ei1   = (const int*)d_in[2];
    const int* ei2   = (const int*)d_in[3];
    const float* Wc1 = (const float*)d_in[6];
    const float* bc1 = (const float*)d_in[7];
    const float* Wc2 = (const float*)d_in[8];
    const float* bc2 = (const float*)d_in[9];
    const float* Wc3 = (const float*)d_in[10];
    const float* bc3 = (const float*)d_in[11];
    const float* Watt = (const float*)d_in[12];
    const float* Wt  = (const float*)d_in[13];
    const float* Wtb = (const float*)d_in[14];
    const float* tb  = (const float*)d_in[15];
    const float* W1  = (const float*)d_in[16];
    const float* b1  = (const float*)d_in[17];
    const float* Ws  = (const float*)d_in[18];
    const float* bs  = (const float*)d_in[19];
    float* out = (float*)d_out;

    void* p;
    float *a0, *a1, *b0, *b1p, *f0, *f1;
    cudaGetSymbolAddress(&p, g_bufA);
    a0 = (float*)p; a1 = a0 + (size_t)NTOT * D_F1;
    cudaGetSymbolAddress(&p, g_bufB);
    b0 = (float*)p; b1p = b0 + (size_t)NTOT * D_F1;
    cudaGetSymbolAddress(&p, g_feat);
    f0 = (float*)p; f1 = f0 + (size_t)NTOT * D_F3;

    init_k<<<NTOT / 256, 256>>>();

    // CSR build for BOTH sides (batched over grid.y)
    deg_k<<<dim3(NEDGE / 256, 2), 256>>>(ei1 + NEDGE, ei2 + NEDGE);
    scanA_k<<<dim3(256, 2), 256>>>();   // also computes dinv
    scanB_k<<<2, 256>>>();
    scanC_k<<<dim3(256, 2), 256>>>();
    scatter_k<<<dim3(NEDGE / 256, 2), 256>>>(ei1, ei2);

    // conv pipeline, both sides per launch
    agg_k<32, false, false><<<dim3(NTOT * 8 / 256, 2), 256>>>(x1, x2, nullptr, a0, a1);
    gemm_mma_k<32, 128, true, true><<<dim3(NTOT / 128, 2), 256>>>(a0, a1, Wc1, bc1, b0, b1p);

    gemm_mma_k<128, 96, false, false><<<dim3(NTOT / 128, 2), 256>>>(b0, b1p, Wc2, nullptr, a0, a1);
    agg_k<96, true, true><<<dim3(NTOT * 24 / 256, 2), 256>>>(a0, a1, bc2, b0, b1p);

    gemm_mma_k<96, 64, false, false><<<dim3(NTOT / 128, 2), 256>>>(b0, b1p, Wc3, nullptr, a0, a1);
    agg_k<64, true, false><<<dim3(NTOT * 16 / 256, 2), 256>>>(a0, a1, bc3, f0, f1);

    pool_k<<<dim3(NB, 2), 256>>>(Watt);

    sim_mma_k<<<dim3(4, 4, NB), 256>>>();
    hist_k<<<dim3(8, NB), 256>>>();
    final_k<<<NB, 128>>>(Wt, Wtb, tb, W1, b1, Ws, bs, out);
}

// round 11
// speedup vs baseline: 1.3580x; 1.0196x over previous
#include <cuda_runtime.h>
#include <cuda_fp16.h>
#include <math.h>
#include <cfloat>
#include <stdint.h>

// ---------------- problem dims (fixed) ----------------
#define NTOT  65536      // nodes per side (B*N)
#define NEDGE 524288     // edges per side
#define NB    128        // graphs
#define NPG   512        // nodes per graph
#define D_F1  128
#define D_F2  96
#define D_F3  64
#define D_BINS 16

// ---------------- device scratch (per-side slabs for batched launches) -----
__device__ float g_bufA[2][NTOT * D_F1];
__device__ float g_bufB[2][NTOT * D_F1];
__device__ float g_feat[2][NTOT * D_F3];
__device__ float g_dinv[2][NTOT];
__device__ int   g_degi[2][NTOT];
__device__ int   g_row[2][NTOT + 1];
__device__ int   g_cursor[2][NTOT];
__device__ int   g_bsum[2][256];
__device__ int2  g_epack[2][NEDGE];                  // {src, norm bits}
__device__ __half g_simh[(size_t)NB * NPG * NPG];   // fp16 similarity scores
__device__ int   g_cdf[NB][15];                      // C[k] = #{s >= thr_{k+1}}
__device__ float g_smin[NB];
__device__ float g_smax[NB];
__device__ float g_pool[2][NB * D_F3];

__device__ __forceinline__ float sigmoidf_(float x) { return 1.0f / (1.0f + expf(-x)); }

__device__ __forceinline__ void atomicMinFloat(float* addr, float val) {
    int old = __float_as_int(*addr);
    while (__int_as_float(old) > val) {
        int assumed = old;
        old = atomicCAS((int*)addr, assumed, __float_as_int(val));
        if (old == assumed) break;
    }
}
__device__ __forceinline__ void atomicMaxFloat(float* addr, float val) {
    int old = __float_as_int(*addr);
    while (__int_as_float(old) < val) {
        int assumed = old;
        old = atomicCAS((int*)addr, assumed, __float_as_int(val));
        if (old == assumed) break;
    }
}

// ---------------- bf16x3 helpers (fp32 emulation via bf16 split) -----------
__device__ __forceinline__ void split2(float x0, float x1, uint32_t& h, uint32_t& l) {
    asm("cvt.rn.bf16x2.f32 %0, %1, %2;" : "=r"(h) : "f"(x1), "f"(x0));
    float r0 = x0 - __uint_as_float(h << 16);
    float r1 = x1 - __uint_as_float(h & 0xffff0000u);
    asm("cvt.rn.bf16x2.f32 %0, %1, %2;" : "=r"(l) : "f"(r1), "f"(r0));
}
__device__ __forceinline__ void mma_bf16(float* d, const uint32_t* a, const uint32_t* b) {
    asm volatile(
        "mma.sync.aligned.m16n8k16.row.col.f32.bf16.bf16.f32 "
        "{%0,%1,%2,%3}, {%4,%5,%6,%7}, {%8,%9}, {%0,%1,%2,%3};\n"
        : "+f"(d[0]), "+f"(d[1]), "+f"(d[2]), "+f"(d[3])
        : "r"(a[0]), "r"(a[1]), "r"(a[2]), "r"(a[3]), "r"(b[0]), "r"(b[1]));
}

// block-wide exclusive scan of 256 ints (one value per thread)
__device__ __forceinline__ int block_exscan_256(int v, int* sm8) {
    int lane = threadIdx.x & 31, w = threadIdx.x >> 5;
    int x = v;
#pragma unroll
    for (int o = 1; o < 32; o <<= 1) {
        int y = __shfl_up_sync(0xffffffffu, x, o);
        if (lane >= o) x += y;
    }
    if (lane == 31) sm8[w] = x;
    __syncthreads();
    if (threadIdx.x < 8) {
        int s = sm8[threadIdx.x];
#pragma unroll
        for (int o = 1; o < 8; o <<= 1) {
            int y = __shfl_up_sync(0xffu, s, o);
            if ((int)threadIdx.x >= o) s += y;
        }
        sm8[threadIdx.x] = s;
    }
    __syncthreads();
    int woff = w ? sm8[w - 1] : 0;
    return woff + x - v;
}

// ---------------- init ----------------
__global__ void init_k() {
    int i = blockIdx.x * blockDim.x + threadIdx.x;
    if (i < NTOT) { g_degi[0][i] = 0; g_degi[1][i] = 0; }
    if (i < NB * 15) g_cdf[i / 15][i % 15] = 0;
    if (i < NB) { g_smin[i] = FLT_MAX; g_smax[i] = -FLT_MAX; }
}

// ---------------- degree (both sides via grid.y) ----------------
__global__ void deg_k(const int* __restrict__ dst0, const int* __restrict__ dst1) {
    int side = blockIdx.y;
    const int* dst = side ? dst1 : dst0;
    int e = blockIdx.x * blockDim.x + threadIdx.x;
    if (e < NEDGE) atomicAdd(&g_degi[side][dst[e]], 1);
}

// ---------------- 2-phase parallel scan (A computes dinv + block sums) -----
__global__ void scanA_k() {
    int side = blockIdx.y;
    int i = blockIdx.x * 256 + threadIdx.x;
    int v = g_degi[side][i];
    g_dinv[side][i] = rsqrtf((float)v + 1.0f);
#pragma unroll
    for (int o = 16; o; o >>= 1) v += __shfl_xor_sync(0xffffffffu, v, o);
    __shared__ int sm[8];
    if ((threadIdx.x & 31) == 0) sm[threadIdx.x >> 5] = v;
    __syncthreads();
    if (threadIdx.x == 0) {
        int s = 0;
#pragma unroll
        for (int j = 0; j < 8; j++) s += sm[j];
        g_bsum[side][blockIdx.x] = s;
    }
}
// scanC: per-block exclusive scan; prefix computed by reducing g_bsum[0..bid)
__global__ void scanC_k() {
    int side = blockIdx.y;
    int bid = blockIdx.x;
    int t = threadIdx.x;
    int lane = t & 31, w = t >> 5;
    // reduce block sums below bid
    int pv = (t < bid) ? g_bsum[side][t] : 0;
#pragma unroll
    for (int o = 16; o; o >>= 1) pv += __shfl_xor_sync(0xffffffffu, pv, o);
    __shared__ int rsm[8];
    if (lane == 0) rsm[w] = pv;
    __syncthreads();
    __shared__ int prefix_s;
    if (t == 0) {
        int s = 0;
#pragma unroll
        for (int j = 0; j < 8; j++) s += rsm[j];
        prefix_s = s;
    }
    __syncthreads();
    int prefix = prefix_s;
    int i = bid * 256 + t;
    int d = g_degi[side][i];
    __shared__ int sm[8];
    int ex = block_exscan_256(d, sm);
    int off = prefix + ex;
    g_row[side][i] = off;
    g_cursor[side][i] = off;
    if (i == NTOT - 1) g_row[side][NTOT] = NEDGE;
}

// ---------------- scatter edges into CSR order (packed src+norm) -----------
__global__ void scatter_k(const int* __restrict__ ei0, const int* __restrict__ ei1) {
    int side = blockIdx.y;
    const int* ei = side ? ei1 : ei0;
    const int* src = ei;
    const int* dst = ei + NEDGE;
    int e = blockIdx.x * blockDim.x + threadIdx.x;
    if (e >= NEDGE) return;
    int s = src[e], d = dst[e];
    int pos = atomicAdd(&g_cursor[side][d], 1);
    float nm = g_dinv[side][s] * g_dinv[side][d];
    g_epack[side][pos] = make_int2(s, __float_as_int(nm));
}

// ---------------- gather-based aggregation (both sides via grid.y) --------
template <int OUT, bool BIAS, bool RELU>
__global__ void agg_k(const float* __restrict__ xw0, const float* __restrict__ xw1,
                      const float* __restrict__ bias,
                      float* __restrict__ out0, float* __restrict__ out1) {
    constexpr int C4 = OUT / 4;
    int side = blockIdx.y;
    const float* xw = side ? xw1 : xw0;
    float* out = side ? out1 : out0;
    int gid = blockIdx.x * blockDim.x + threadIdx.x;
    int node = gid / C4, chunk = gid % C4;
    if (node >= NTOT) return;
    const float4* xw4 = (const float4*)xw;
    float dv = g_dinv[side][node];
    float dv2 = dv * dv;
    float4 v = xw4[(size_t)node * C4 + chunk];
    float4 acc = make_float4(v.x * dv2, v.y * dv2, v.z * dv2, v.w * dv2);
    int beg = g_row[side][node], end = g_row[side][node + 1];
    for (int e = beg; e < end; e++) {
        int2 ep = g_epack[side][e];
        float nm = __int_as_float(ep.y);
        float4 u = xw4[(size_t)ep.x * C4 + chunk];
        acc.x += u.x * nm; acc.y += u.y * nm; acc.z += u.z * nm; acc.w += u.w * nm;
    }
    if (BIAS) {
        acc.x += bias[chunk * 4 + 0];
        acc.y += bias[chunk * 4 + 1];
        acc.z += bias[chunk * 4 + 2];
        acc.w += bias[chunk * 4 + 3];
    }
    if (RELU) {
        acc.x = fmaxf(acc.x, 0.f); acc.y = fmaxf(acc.y, 0.f);
        acc.z = fmaxf(acc.z, 0.f); acc.w = fmaxf(acc.w, 0.f);
    }
    ((float4*)out)[(size_t)node * C4 + chunk] = acc;
}

// ---------------- bf16x3 tensor-core GEMM (both sides via grid.y) ----------
template <int KIN, int NOUT, bool BIAS, bool RELU>
__global__ void gemm_mma_k(const float* __restrict__ x0, const float* __restrict__ x1,
                           const float* __restrict__ W, const float* __restrict__ bias,
                           float* __restrict__ out0, float* __restrict__ out1) {
    constexpr int KC = 32;
    constexpr int KP = KC / 2;
    constexpr int NT = NOUT / 8;
    constexpr int XS = 20;
    constexpr int WS = 20;
    __shared__ uint32_t Xh[128 * XS];
    __shared__ uint32_t Xl[128 * XS];
    __shared__ uint32_t Wh[NOUT * WS];
    __shared__ uint32_t Wl[NOUT * WS];
    int side = blockIdx.y;
    const float* x = side ? x1 : x0;
    float* out = side ? out1 : out0;
    int tid = threadIdx.x;
    int warp = tid >> 5, lane = tid & 31;
    size_t m0 = (size_t)blockIdx.x * 128;
    float acc[NT][4];
#pragma unroll
    for (int i = 0; i < NT; i++)
#pragma unroll
        for (int j = 0; j < 4; j++) acc[i][j] = 0.0f;

    for (int k0 = 0; k0 < KIN; k0 += KC) {
        for (int i = tid; i < 128 * 8; i += 256) {
            int r = i >> 3, q = i & 7;
            float4 v = *(const float4*)&x[(m0 + r) * KIN + k0 + q * 4];
            uint32_t h0, l0, h1, l1;
            split2(v.x, v.y, h0, l0);
            split2(v.z, v.w, h1, l1);
            Xh[r * XS + q * 2] = h0;     Xh[r * XS + q * 2 + 1] = h1;
            Xl[r * XS + q * 2] = l0;     Xl[r * XS + q * 2 + 1] = l1;
        }
        for (int i = tid; i < NOUT * KP; i += 256) {
            int kp = i / NOUT, n = i % NOUT;
            float w0 = W[(size_t)(k0 + 2 * kp) * NOUT + n];
            float w1 = W[(size_t)(k0 + 2 * kp + 1) * NOUT + n];
            uint32_t h, l;
            split2(w0, w1, h, l);
            Wh[n * WS + kp] = h;
            Wl[n * WS + kp] = l;
        }
        __syncthreads();
#pragma unroll
        for (int s = 0; s < 2; s++) {
            int kb = s * 8 + (lane & 3);
            uint32_t ah[4], al[4];
            int arow = warp * 16 + (lane >> 2);
            ah[0] = Xh[arow * XS + kb];           al[0] = Xl[arow * XS + kb];
            ah[1] = Xh[(arow + 8) * XS + kb];     al[1] = Xl[(arow + 8) * XS + kb];
            ah[2] = Xh[arow * XS + kb + 4];       al[2] = Xl[arow * XS + kb + 4];
            ah[3] = Xh[(arow + 8) * XS + kb + 4]; al[3] = Xl[(arow + 8) * XS + kb + 4];
            int bn = lane >> 2;
#pragma unroll
            for (int nt = 0; nt < NT; nt++) {
                uint32_t bh[2], bl[2];
                int nb = (nt * 8 + bn) * WS;
                bh[0] = Wh[nb + kb]; bh[1] = Wh[nb + kb + 4];
                bl[0] = Wl[nb + kb]; bl[1] = Wl[nb + kb + 4];
                mma_bf16(acc[nt], ah, bh);
                mma_bf16(acc[nt], ah, bl);
                mma_bf16(acc[nt], al, bh);
            }
        }
        __syncthreads();
    }
    size_t row = m0 + warp * 16 + (lane >> 2);
    int col0 = (lane & 3) * 2;
#pragma unroll
    for (int nt = 0; nt < NT; nt++) {
        int c = nt * 8 + col0;
        float b0 = BIAS ? bias[c] : 0.0f, b1 = BIAS ? bias[c + 1] : 0.0f;
        float v0 = acc[nt][0] + b0, v1 = acc[nt][1] + b1;
        float v2 = acc[nt][2] + b0, v3 = acc[nt][3] + b1;
        if (RELU) {
            v0 = fmaxf(v0, 0.f); v1 = fmaxf(v1, 0.f);
            v2 = fmaxf(v2, 0.f); v3 = fmaxf(v3, 0.f);
        }
        *(float2*)&out[row * NOUT + c] = make_float2(v0, v1);
        *(float2*)&out[(row + 8) * NOUT + c] = make_float2(v2, v3);
    }
}

// ---------------- attention pooling (grid = (NB, 2)) ----------------
__global__ void pool_k(const float* __restrict__ Watt) {
    int side = blockIdx.y;
    int b = blockIdx.x;
    const float* fb = &g_feat[side][(size_t)b * NPG * D_F3];
    int t = threadIdx.x;  // 256
    __shared__ float p4[4][64];
    __shared__ float meanc[64];
    __shared__ float ctx[64];
    __shared__ float wsum[8][64];
    int d = t & 63, g = t >> 6;
    float loc = 0.0f;
    for (int r = g; r < NPG; r += 4) loc += fb[r * 64 + d];
    p4[g][d] = loc;
    __syncthreads();
    if (t < 64) meanc[t] = (p4[0][t] + p4[1][t] + p4[2][t] + p4[3][t]) * (1.0f / NPG);
    __syncthreads();
    if (t < 64) {
        float c = 0.0f;
        for (int i = 0; i < 64; i++) c += meanc[i] * Watt[i * 64 + t];
        ctx[t] = tanhf(c);
    }
    __syncthreads();
    int w = t >> 5, l = t & 31;
    float a0 = 0.0f, a1 = 0.0f;
    float c0 = ctx[l], c1 = ctx[l + 32];
    for (int r = w * 64; r < w * 64 + 64; r++) {
        float v0 = fb[r * 64 + l], v1 = fb[r * 64 + 32 + l];
        float dp = v0 * c0 + v1 * c1;
#pragma unroll
        for (int o = 16; o; o >>= 1) dp += __shfl_xor_sync(0xffffffffu, dp, o);
        float coef = sigmoidf_(dp);
        a0 += v0 * coef;
        a1 += v1 * coef;
    }
    wsum[w][l] = a0;
    wsum[w][l + 32] = a1;
    __syncthreads();
    if (t < 64) {
        float s = 0.0f;
        for (int w2 = 0; w2 < 8; w2++) s += wsum[w2][t];
        g_pool[side][b * 64 + t] = s;
    }
}

// ---------------- similarity via bf16x3 mma, 128x128 tile, fp16 store ------
__global__ void sim_mma_k() {
    constexpr int XS = 20;
    int b = blockIdx.z;
    int i0 = blockIdx.y * 128, j0 = blockIdx.x * 128;
    __shared__ uint32_t Ah_s[128 * XS];
    __shared__ uint32_t Al_s[128 * XS];
    __shared__ uint32_t Bh_s[128 * XS];
    __shared__ uint32_t Bl_s[128 * XS];
    const float* f1 = &g_feat[0][(size_t)(b * NPG + i0) * 64];
    const float* f2 = &g_feat[1][(size_t)(b * NPG + j0) * 64];
    int tid = threadIdx.x;
    int warp = tid >> 5, lane = tid & 31;
    int wm = warp >> 2, wn = warp & 3;
    float acc[4][4][4];
#pragma unroll
    for (int mt = 0; mt < 4; mt++)
#pragma unroll
        for (int nt = 0; nt < 4; nt++)
#pragma unroll
            for (int j = 0; j < 4; j++) acc[mt][nt][j] = 0.0f;

    for (int k0 = 0; k0 < 64; k0 += 32) {
        for (int i = tid; i < 128 * 8; i += 256) {
            int r = i >> 3, q = i & 7;
            float4 va = *(const float4*)&f1[r * 64 + k0 + q * 4];
            float4 vb = *(const float4*)&f2[r * 64 + k0 + q * 4];
            uint32_t h0, l0, h1, l1;
            split2(va.x, va.y, h0, l0);
            split2(va.z, va.w, h1, l1);
            Ah_s[r * XS + q * 2] = h0;     Ah_s[r * XS + q * 2 + 1] = h1;
            Al_s[r * XS + q * 2] = l0;     Al_s[r * XS + q * 2 + 1] = l1;
            split2(vb.x, vb.y, h0, l0);
            split2(vb.z, vb.w, h1, l1);
            Bh_s[r * XS + q * 2] = h0;     Bh_s[r * XS + q * 2 + 1] = h1;
            Bl_s[r * XS + q * 2] = l0;     Bl_s[r * XS + q * 2 + 1] = l1;
        }
        __syncthreads();
#pragma unroll
        for (int s = 0; s < 2; s++) {
            int kb = s * 8 + (lane & 3);
            uint32_t ah[4][4], al[4][4], bh[4][2], bl[4][2];
#pragma unroll
            for (int mt = 0; mt < 4; mt++) {
                int arow = wm * 64 + mt * 16 + (lane >> 2);
                ah[mt][0] = Ah_s[arow * XS + kb];
                ah[mt][1] = Ah_s[(arow + 8) * XS + kb];
                ah[mt][2] = Ah_s[arow * XS + kb + 4];
                ah[mt][3] = Ah_s[(arow + 8) * XS + kb + 4];
                al[mt][0] = Al_s[arow * XS + kb];
                al[mt][1] = Al_s[(arow + 8) * XS + kb];
                al[mt][2] = Al_s[arow * XS + kb + 4];
                al[mt][3] = Al_s[(arow + 8) * XS + kb + 4];
            }
#pragma unroll
            for (int nt = 0; nt < 4; nt++) {
                int bnode = wn * 32 + nt * 8 + (lane >> 2);
                bh[nt][0] = Bh_s[bnode * XS + kb];
                bh[nt][1] = Bh_s[bnode * XS + kb + 4];
                bl[nt][0] = Bl_s[bnode * XS + kb];
                bl[nt][1] = Bl_s[bnode * XS + kb + 4];
            }
#pragma unroll
            for (int mt = 0; mt < 4; mt++)
#pragma unroll
                for (int nt = 0; nt < 4; nt++) {
                    mma_bf16(acc[mt][nt], ah[mt], bh[nt]);
                    mma_bf16(acc[mt][nt], ah[mt], bl[nt]);
                    mma_bf16(acc[mt][nt], al[mt], bh[nt]);
                }
        }
        __syncthreads();
    }
    float lmin = FLT_MAX, lmax = -FLT_MAX;
    __half* sp = &g_simh[(size_t)b * NPG * NPG];
    int col0 = (lane & 3) * 2;
#pragma unroll
    for (int mt = 0; mt < 4; mt++) {
        size_t r0 = (size_t)(i0 + wm * 64 + mt * 16 + (lane >> 2));
#pragma unroll
        for (int nt = 0; nt < 4; nt++) {
            int c = j0 + wn * 32 + nt * 8 + col0;
            float v0 = acc[mt][nt][0], v1 = acc[mt][nt][1];
            float v2 = acc[mt][nt][2], v3 = acc[mt][nt][3];
            lmin = fminf(lmin, fminf(fminf(v0, v1), fminf(v2, v3)));
            lmax = fmaxf(lmax, fmaxf(fmaxf(v0, v1), fmaxf(v2, v3)));
            *(__half2*)&sp[r0 * NPG + c] = __floats2half2_rn(v0, v1);
            *(__half2*)&sp[(r0 + 8) * NPG + c] = __floats2half2_rn(v2, v3);
        }
    }
    __shared__ float rmin[256], rmax[256];
    rmin[tid] = lmin;
    rmax[tid] = lmax;
    __syncthreads();
    for (int s = 128; s > 0; s >>= 1) {
        if (tid < s) {
            rmin[tid] = fminf(rmin[tid], rmin[tid + s]);
            rmax[tid] = fmaxf(rmax[tid], rmax[tid + s]);
        }
        __syncthreads();
    }
    if (tid == 0) {
        atomicMinFloat(&g_smin[b], rmin[0]);
        atomicMaxFloat(&g_smax[b], rmax[0]);
    }
}

// ---------------- histogram via threshold CDF, half2 SIMD compares ---------
__global__ void hist_k() {
    int b = blockIdx.y;
    int part = blockIdx.x;               // 8 parts per graph
    int t = threadIdx.x;
    int lane = t & 31, warp = t >> 5;    // 8 warps
    __shared__ __half2 thr_s[15];
    if (t < 15) {
        float vmin = sigmoidf_(g_smin[b]);
        float vmax = sigmoidf_(g_smax[b]);
        float width = (vmax - vmin) * (1.0f / D_BINS);
        float thr;
        if (width > 0.0f) {
            float bnd = vmin + (float)(t + 1) * width;
            thr = logf(bnd / (1.0f - bnd));
        } else {
            thr = FLT_MAX;                 // -> +inf in half: all compares false
        }
        thr_s[t] = __float2half2_rn(thr);
    }
    __syncthreads();
    __half2 T2[15];
#pragma unroll
    for (int k = 0; k < 15; k++) T2[k] = thr_s[k];

    const uint4* qp = (const uint4*)&g_simh[(size_t)b * NPG * NPG] + part * 4096;
    __half2 C2[15];
#pragma unroll
    for (int k = 0; k < 15; k++) C2[k] = __float2half2_rn(0.0f);
    // each thread: 16 iterations x 8 values; per-half counters <= 64 (exact fp16)
    for (int i = t; i < 4096; i += 256) {
        uint4 q = qp[i];
        __half2 h0 = *(__half2*)&q.x;
        __half2 h1 = *(__half2*)&q.y;
        __half2 h2 = *(__half2*)&q.z;
        __half2 h3 = *(__half2*)&q.w;
#pragma unroll
        for (int k = 0; k < 15; k++) {
            C2[k] = __hadd2(C2[k], __hge2(h0, T2[k]));
            C2[k] = __hadd2(C2[k], __hge2(h1, T2[k]));
            C2[k] = __hadd2(C2[k], __hge2(h2, T2[k]));
            C2[k] = __hadd2(C2[k], __hge2(h3, T2[k]));
        }
    }
    __shared__ int red[8][15];
#pragma unroll
    for (int k = 0; k < 15; k++) {
        int c = (int)(__low2float(C2[k]) + __high2float(C2[k]));
#pragma unroll
        for (int o = 16; o; o >>= 1) c += __shfl_xor_sync(0xffffffffu, c, o);
        if (lane == 0) red[warp][k] = c;
    }
    __syncthreads();
    if (t < 15) {
        int s = 0;
#pragma unroll
        for (int w = 0; w < 8; w++) s += red[w][t];
        atomicAdd(&g_cdf[b][t], s);
    }
}

// ---------------- final head (one block per graph, 128 threads) ----------
__global__ void final_k(const float* __restrict__ Wt, const float* __restrict__ Wtb,
                        const float* __restrict__ tb, const float* __restrict__ W1,
                        const float* __restrict__ b1, const float* __restrict__ Ws,
                        const float* __restrict__ bs, float* __restrict__ out) {
    int b = blockIdx.x, t = threadIdx.x;
    __shared__ float p1s[64], p2s[64];
    __shared__ float scp[64 * 16];
    __shared__ float feat[32];
    __shared__ float hs[32];
    if (t < 64) {
        p1s[t] = g_pool[0][b * 64 + t];
        p2s[t] = g_pool[1][b * 64 + t];
    }
    __syncthreads();
    if (t < 64) {
        float s[16];
#pragma unroll
        for (int k = 0; k < 16; k++) s[k] = 0.0f;
        for (int j = 0; j < 64; j++) {
            float pj = p2s[j];
            const float* wp = &Wt[(size_t)(t * 64 + j) * 16];
#pragma unroll
            for (int k = 0; k < 16; k++) s[k] += wp[k] * pj;
        }
        float p1v = p1s[t];
#pragma unroll
        for (int k = 0; k < 16; k++) scp[t * 16 + k] = p1v * s[k];
    }
    __syncthreads();
    if (t < 16) {
        float acc = tb[t];
        for (int i = 0; i < 64; i++) acc += scp[i * 16 + t];
        float blk = 0.0f;
        for (int i = 0; i < 64; i++) blk += Wtb[t * 128 + i] * p1s[i];
        for (int i = 0; i < 64; i++) blk += Wtb[t * 128 + 64 + i] * p2s[i];
        float tv = acc + blk;
        feat[t] = fmaxf(tv, 0.0f);
        int C_lo = (t == 0) ? NPG * NPG : g_cdf[b][t - 1];
        int C_hi = (t == 15) ? 0 : g_cdf[b][t];
        feat[16 + t] = (float)(C_lo - C_hi) * (1.0f / ((float)NPG * (float)NPG));
    }
    __syncthreads();
    if (t < 32) {
        float acc = b1[t];
        for (int i = 0; i < 32; i++) acc += feat[i] * W1[i * 32 + t];
        hs[t] = fmaxf(acc, 0.0f);
    }
    __syncthreads();
    if (t == 0) {
        float acc = bs[0];
        for (int j = 0; j < 32; j++) acc += hs[j] * Ws[j];
        out[b] = sigmoidf_(acc);
    }
}

// ---------------- launcher ----------------
extern "C" void kernel_launch(void* const* d_in, const int* in_sizes, int n_in,
                              void* d_out, int out_size) {
    const float* x1  = (const float*)d_in[0];
    const float* x2  = (const float*)d_in[1];
    const int* ei1   = (const int*)d_in[2];
    const int* ei2   = (const int*)d_in[3];
    const float* Wc1 = (const float*)d_in[6];
    const float* bc1 = (const float*)d_in[7];
    const float* Wc2 = (const float*)d_in[8];
    const float* bc2 = (const float*)d_in[9];
    const float* Wc3 = (const float*)d_in[10];
    const float* bc3 = (const float*)d_in[11];
    const float* Watt = (const float*)d_in[12];
    const float* Wt  = (const float*)d_in[13];
    const float* Wtb = (const float*)d_in[14];
    const float* tb  = (const float*)d_in[15];
    const float* W1  = (const float*)d_in[16];
    const float* b1  = (const float*)d_in[17];
    const float* Ws  = (const float*)d_in[18];
    const float* bs  = (const float*)d_in[19];
    float* out = (float*)d_out;

    void* p;
    float *a0, *a1, *b0, *b1p, *f0, *f1;
    cudaGetSymbolAddress(&p, g_bufA);
    a0 = (float*)p; a1 = a0 + (size_t)NTOT * D_F1;
    cudaGetSymbolAddress(&p, g_bufB);
    b0 = (float*)p; b1p = b0 + (size_t)NTOT * D_F1;
    cudaGetSymbolAddress(&p, g_feat);
    f0 = (float*)p; f1 = f0 + (size_t)NTOT * D_F3;

    init_k<<<NTOT / 256, 256>>>();

    // CSR build for BOTH sides (batched over grid.y)
    deg_k<<<dim3(NEDGE / 256, 2), 256>>>(ei1 + NEDGE, ei2 + NEDGE);
    scanA_k<<<dim3(256, 2), 256>>>();   // also computes dinv
    scanC_k<<<dim3(256, 2), 256>>>();   // prefix via bsum reduce (scanB merged)
    scatter_k<<<dim3(NEDGE / 256, 2), 256>>>(ei1, ei2);

    // conv pipeline, both sides per launch
    agg_k<32, false, false><<<dim3(NTOT * 8 / 256, 2), 256>>>(x1, x2, nullptr, a0, a1);
    gemm_mma_k<32, 128, true, true><<<dim3(NTOT / 128, 2), 256>>>(a0, a1, Wc1, bc1, b0, b1p);

    gemm_mma_k<128, 96, false, false><<<dim3(NTOT / 128, 2), 256>>>(b0, b1p, Wc2, nullptr, a0, a1);
    agg_k<96, true, true><<<dim3(NTOT * 24 / 256, 2), 256>>>(a0, a1, bc2, b0, b1p);

    gemm_mma_k<96, 64, false, false><<<dim3(NTOT / 128, 2), 256>>>(b0, b1p, Wc3, nullptr, a0, a1);
    agg_k<64, true, false><<<dim3(NTOT * 16 / 256, 2), 256>>>(a0, a1, bc3, f0, f1);

    pool_k<<<dim3(NB, 2), 256>>>(Watt);

    sim_mma_k<<<dim3(4, 4, NB), 256>>>();
    hist_k<<<dim3(8, NB), 256>>>();
    final_k<<<NB, 128>>>(Wt, Wtb, tb, W1, b1, Ws, bs, out);
}

// round 12
// speedup vs baseline: 1.4328x; 1.0551x over previous
#include <cuda_runtime.h>
#include <cuda_fp16.h>
#include <math.h>
#include <cfloat>
#include <stdint.h>

// ---------------- problem dims (fixed) ----------------
#define NTOT  65536      // nodes per side (B*N)
#define NEDGE 524288     // edges per side
#define NB    128        // graphs
#define NPG   512        // nodes per graph
#define D_F1  128
#define D_F2  96
#define D_F3  64
#define D_BINS 16

// ---------------- device scratch (per-side slabs for batched launches) -----
__device__ float g_bufA[2][NTOT * D_F1];
__device__ float g_bufB[2][NTOT * D_F1];
__device__ float g_feat[2][NTOT * D_F3];
__device__ float g_dinv[2][NTOT];
__device__ int   g_degi[2][NTOT];
__device__ int   g_row[2][NTOT + 1];
__device__ int   g_cursor[2][NTOT];
__device__ int   g_bsum[2][256];
__device__ int2  g_epack[2][NEDGE];                  // {src, norm bits}
__device__ __half g_simh[(size_t)NB * NPG * NPG];   // fp16 similarity scores
__device__ int   g_cdf[NB][15];                      // C[k] = #{s >= thr_{k+1}}
__device__ float g_smin[NB];
__device__ float g_smax[NB];
__device__ float g_pool[2][NB * D_F3];

__device__ __forceinline__ float sigmoidf_(float x) { return 1.0f / (1.0f + expf(-x)); }

__device__ __forceinline__ void atomicMinFloat(float* addr, float val) {
    int old = __float_as_int(*addr);
    while (__int_as_float(old) > val) {
        int assumed = old;
        old = atomicCAS((int*)addr, assumed, __float_as_int(val));
        if (old == assumed) break;
    }
}
__device__ __forceinline__ void atomicMaxFloat(float* addr, float val) {
    int old = __float_as_int(*addr);
    while (__int_as_float(old) < val) {
        int assumed = old;
        old = atomicCAS((int*)addr, assumed, __float_as_int(val));
        if (old == assumed) break;
    }
}

// ---------------- bf16x3 helpers (fp32 emulation via bf16 split) -----------
__device__ __forceinline__ void split2(float x0, float x1, uint32_t& h, uint32_t& l) {
    asm("cvt.rn.bf16x2.f32 %0, %1, %2;" : "=r"(h) : "f"(x1), "f"(x0));
    float r0 = x0 - __uint_as_float(h << 16);
    float r1 = x1 - __uint_as_float(h & 0xffff0000u);
    asm("cvt.rn.bf16x2.f32 %0, %1, %2;" : "=r"(l) : "f"(r1), "f"(r0));
}
__device__ __forceinline__ void mma_bf16(float* d, const uint32_t* a, const uint32_t* b) {
    asm volatile(
        "mma.sync.aligned.m16n8k16.row.col.f32.bf16.bf16.f32 "
        "{%0,%1,%2,%3}, {%4,%5,%6,%7}, {%8,%9}, {%0,%1,%2,%3};\n"
        : "+f"(d[0]), "+f"(d[1]), "+f"(d[2]), "+f"(d[3])
        : "r"(a[0]), "r"(a[1]), "r"(a[2]), "r"(a[3]), "r"(b[0]), "r"(b[1]));
}

// block-wide exclusive scan of 256 ints (one value per thread)
__device__ __forceinline__ int block_exscan_256(int v, int* sm8) {
    int lane = threadIdx.x & 31, w = threadIdx.x >> 5;
    int x = v;
#pragma unroll
    for (int o = 1; o < 32; o <<= 1) {
        int y = __shfl_up_sync(0xffffffffu, x, o);
        if (lane >= o) x += y;
    }
    if (lane == 31) sm8[w] = x;
    __syncthreads();
    if (threadIdx.x < 8) {
        int s = sm8[threadIdx.x];
#pragma unroll
        for (int o = 1; o < 8; o <<= 1) {
            int y = __shfl_up_sync(0xffu, s, o);
            if ((int)threadIdx.x >= o) s += y;
        }
        sm8[threadIdx.x] = s;
    }
    __syncthreads();
    int woff = w ? sm8[w - 1] : 0;
    return woff + x - v;
}

// ---------------- init ----------------
__global__ void init_k() {
    int i = blockIdx.x * blockDim.x + threadIdx.x;
    if (i < NTOT) { g_degi[0][i] = 0; g_degi[1][i] = 0; }
    if (i < NB * 15) g_cdf[i / 15][i % 15] = 0;
    if (i < NB) { g_smin[i] = FLT_MAX; g_smax[i] = -FLT_MAX; }
}

// ---------------- degree (both sides via grid.y) ----------------
__global__ void deg_k(const int* __restrict__ dst0, const int* __restrict__ dst1) {
    int side = blockIdx.y;
    const int* dst = side ? dst1 : dst0;
    int e = blockIdx.x * blockDim.x + threadIdx.x;
    if (e < NEDGE) atomicAdd(&g_degi[side][dst[e]], 1);
}

// ---------------- 2-phase parallel scan (A computes dinv + block sums) -----
__global__ void scanA_k() {
    int side = blockIdx.y;
    int i = blockIdx.x * 256 + threadIdx.x;
    int v = g_degi[side][i];
    g_dinv[side][i] = rsqrtf((float)v + 1.0f);
#pragma unroll
    for (int o = 16; o; o >>= 1) v += __shfl_xor_sync(0xffffffffu, v, o);
    __shared__ int sm[8];
    if ((threadIdx.x & 31) == 0) sm[threadIdx.x >> 5] = v;
    __syncthreads();
    if (threadIdx.x == 0) {
        int s = 0;
#pragma unroll
        for (int j = 0; j < 8; j++) s += sm[j];
        g_bsum[side][blockIdx.x] = s;
    }
}
// scanC: per-block exclusive scan; prefix computed by reducing g_bsum[0..bid)
__global__ void scanC_k() {
    int side = blockIdx.y;
    int bid = blockIdx.x;
    int t = threadIdx.x;
    int lane = t & 31, w = t >> 5;
    int pv = (t < bid) ? g_bsum[side][t] : 0;
#pragma unroll
    for (int o = 16; o; o >>= 1) pv += __shfl_xor_sync(0xffffffffu, pv, o);
    __shared__ int rsm[8];
    if (lane == 0) rsm[w] = pv;
    __syncthreads();
    __shared__ int prefix_s;
    if (t == 0) {
        int s = 0;
#pragma unroll
        for (int j = 0; j < 8; j++) s += rsm[j];
        prefix_s = s;
    }
    __syncthreads();
    int prefix = prefix_s;
    int i = bid * 256 + t;
    int d = g_degi[side][i];
    __shared__ int sm[8];
    int ex = block_exscan_256(d, sm);
    int off = prefix + ex;
    g_row[side][i] = off;
    g_cursor[side][i] = off;
    if (i == NTOT - 1) g_row[side][NTOT] = NEDGE;
}

// ---------------- scatter edges into CSR order (packed src+norm) -----------
__global__ void scatter_k(const int* __restrict__ ei0, const int* __restrict__ ei1) {
    int side = blockIdx.y;
    const int* ei = side ? ei1 : ei0;
    const int* src = ei;
    const int* dst = ei + NEDGE;
    int e = blockIdx.x * blockDim.x + threadIdx.x;
    if (e >= NEDGE) return;
    int s = src[e], d = dst[e];
    int pos = atomicAdd(&g_cursor[side][d], 1);
    float nm = g_dinv[side][s] * g_dinv[side][d];
    g_epack[side][pos] = make_int2(s, __float_as_int(nm));
}

// ---------------- graph-per-block aggregation (L1-resident gathers) --------
// One 1024-thread block per graph: the graph's feature slab (<=196KB) becomes
// L1-resident after first touch, so the ~8x edge re-reads hit L1 not L2.
template <int OUT, bool BIAS, bool RELU>
__global__ void agg_k(const float* __restrict__ xw0, const float* __restrict__ xw1,
                      const float* __restrict__ bias,
                      float* __restrict__ out0, float* __restrict__ out1) {
    constexpr int C4 = OUT / 4;
    int side = blockIdx.y;
    const float* xw = side ? xw1 : xw0;
    float* out = side ? out1 : out0;
    int base = blockIdx.x * NPG;
    const float4* xw4 = (const float4*)xw;
    float4* out4 = (float4*)out;
    for (int wi = threadIdx.x; wi < NPG * C4; wi += blockDim.x) {
        int node = base + wi / C4;
        int chunk = wi % C4;
        float dv = g_dinv[side][node];
        float dv2 = dv * dv;
        float4 v = xw4[(size_t)node * C4 + chunk];
        float4 acc = make_float4(v.x * dv2, v.y * dv2, v.z * dv2, v.w * dv2);
        int beg = g_row[side][node], end = g_row[side][node + 1];
        for (int e = beg; e < end; e++) {
            int2 ep = g_epack[side][e];
            float nm = __int_as_float(ep.y);
            float4 u = xw4[(size_t)ep.x * C4 + chunk];
            acc.x += u.x * nm; acc.y += u.y * nm; acc.z += u.z * nm; acc.w += u.w * nm;
        }
        if (BIAS) {
            acc.x += bias[chunk * 4 + 0];
            acc.y += bias[chunk * 4 + 1];
            acc.z += bias[chunk * 4 + 2];
            acc.w += bias[chunk * 4 + 3];
        }
        if (RELU) {
            acc.x = fmaxf(acc.x, 0.f); acc.y = fmaxf(acc.y, 0.f);
            acc.z = fmaxf(acc.z, 0.f); acc.w = fmaxf(acc.w, 0.f);
        }
        out4[(size_t)node * C4 + chunk] = acc;
    }
}

// ---------------- bf16x3 tensor-core GEMM (both sides via grid.y) ----------
template <int KIN, int NOUT, bool BIAS, bool RELU>
__global__ void gemm_mma_k(const float* __restrict__ x0, const float* __restrict__ x1,
                           const float* __restrict__ W, const float* __restrict__ bias,
                           float* __restrict__ out0, float* __restrict__ out1) {
    constexpr int KC = 32;
    constexpr int KP = KC / 2;
    constexpr int NT = NOUT / 8;
    constexpr int XS = 20;
    constexpr int WS = 20;
    __shared__ uint32_t Xh[128 * XS];
    __shared__ uint32_t Xl[128 * XS];
    __shared__ uint32_t Wh[NOUT * WS];
    __shared__ uint32_t Wl[NOUT * WS];
    int side = blockIdx.y;
    const float* x = side ? x1 : x0;
    float* out = side ? out1 : out0;
    int tid = threadIdx.x;
    int warp = tid >> 5, lane = tid & 31;
    size_t m0 = (size_t)blockIdx.x * 128;
    float acc[NT][4];
#pragma unroll
    for (int i = 0; i < NT; i++)
#pragma unroll
        for (int j = 0; j < 4; j++) acc[i][j] = 0.0f;

    for (int k0 = 0; k0 < KIN; k0 += KC) {
        for (int i = tid; i < 128 * 8; i += 256) {
            int r = i >> 3, q = i & 7;
            float4 v = *(const float4*)&x[(m0 + r) * KIN + k0 + q * 4];
            uint32_t h0, l0, h1, l1;
            split2(v.x, v.y, h0, l0);
            split2(v.z, v.w, h1, l1);
            Xh[r * XS + q * 2] = h0;     Xh[r * XS + q * 2 + 1] = h1;
            Xl[r * XS + q * 2] = l0;     Xl[r * XS + q * 2 + 1] = l1;
        }
        for (int i = tid; i < NOUT * KP; i += 256) {
            int kp = i / NOUT, n = i % NOUT;
            float w0 = W[(size_t)(k0 + 2 * kp) * NOUT + n];
            float w1 = W[(size_t)(k0 + 2 * kp + 1) * NOUT + n];
            uint32_t h, l;
            split2(w0, w1, h, l);
            Wh[n * WS + kp] = h;
            Wl[n * WS + kp] = l;
        }
        __syncthreads();
#pragma unroll
        for (int s = 0; s < 2; s++) {
            int kb = s * 8 + (lane & 3);
            uint32_t ah[4], al[4];
            int arow = warp * 16 + (lane >> 2);
            ah[0] = Xh[arow * XS + kb];           al[0] = Xl[arow * XS + kb];
            ah[1] = Xh[(arow + 8) * XS + kb];     al[1] = Xl[(arow + 8) * XS + kb];
            ah[2] = Xh[arow * XS + kb + 4];       al[2] = Xl[arow * XS + kb + 4];
            ah[3] = Xh[(arow + 8) * XS + kb + 4]; al[3] = Xl[(arow + 8) * XS + kb + 4];
            int bn = lane >> 2;
#pragma unroll
            for (int nt = 0; nt < NT; nt++) {
                uint32_t bh[2], bl[2];
                int nb = (nt * 8 + bn) * WS;
                bh[0] = Wh[nb + kb]; bh[1] = Wh[nb + kb + 4];
                bl[0] = Wl[nb + kb]; bl[1] = Wl[nb + kb + 4];
                mma_bf16(acc[nt], ah, bh);
                mma_bf16(acc[nt], ah, bl);
                mma_bf16(acc[nt], al, bh);
            }
        }
        __syncthreads();
    }
    size_t row = m0 + warp * 16 + (lane >> 2);
    int col0 = (lane & 3) * 2;
#pragma unroll
    for (int nt = 0; nt < NT; nt++) {
        int c = nt * 8 + col0;
        float b0 = BIAS ? bias[c] : 0.0f, b1 = BIAS ? bias[c + 1] : 0.0f;
        float v0 = acc[nt][0] + b0, v1 = acc[nt][1] + b1;
        float v2 = acc[nt][2] + b0, v3 = acc[nt][3] + b1;
        if (RELU) {
            v0 = fmaxf(v0, 0.f); v1 = fmaxf(v1, 0.f);
            v2 = fmaxf(v2, 0.f); v3 = fmaxf(v3, 0.f);
        }
        *(float2*)&out[row * NOUT + c] = make_float2(v0, v1);
        *(float2*)&out[(row + 8) * NOUT + c] = make_float2(v2, v3);
    }
}

// ---------------- attention pooling (grid = (NB, 2)) ----------------
__global__ void pool_k(const float* __restrict__ Watt) {
    int side = blockIdx.y;
    int b = blockIdx.x;
    const float* fb = &g_feat[side][(size_t)b * NPG * D_F3];
    int t = threadIdx.x;  // 256
    __shared__ float p4[4][64];
    __shared__ float meanc[64];
    __shared__ float ctx[64];
    __shared__ float wsum[8][64];
    int d = t & 63, g = t >> 6;
    float loc = 0.0f;
    for (int r = g; r < NPG; r += 4) loc += fb[r * 64 + d];
    p4[g][d] = loc;
    __syncthreads();
    if (t < 64) meanc[t] = (p4[0][t] + p4[1][t] + p4[2][t] + p4[3][t]) * (1.0f / NPG);
    __syncthreads();
    if (t < 64) {
        float c = 0.0f;
        for (int i = 0; i < 64; i++) c += meanc[i] * Watt[i * 64 + t];
        ctx[t] = tanhf(c);
    }
    __syncthreads();
    int w = t >> 5, l = t & 31;
    float a0 = 0.0f, a1 = 0.0f;
    float c0 = ctx[l], c1 = ctx[l + 32];
    for (int r = w * 64; r < w * 64 + 64; r++) {
        float v0 = fb[r * 64 + l], v1 = fb[r * 64 + 32 + l];
        float dp = v0 * c0 + v1 * c1;
#pragma unroll
        for (int o = 16; o; o >>= 1) dp += __shfl_xor_sync(0xffffffffu, dp, o);
        float coef = sigmoidf_(dp);
        a0 += v0 * coef;
        a1 += v1 * coef;
    }
    wsum[w][l] = a0;
    wsum[w][l + 32] = a1;
    __syncthreads();
    if (t < 64) {
        float s = 0.0f;
        for (int w2 = 0; w2 < 8; w2++) s += wsum[w2][t];
        g_pool[side][b * 64 + t] = s;
    }
}

// ---------------- similarity via bf16x3 mma, 128x128 tile, fp16 store ------
__global__ void sim_mma_k() {
    constexpr int XS = 20;
    int b = blockIdx.z;
    int i0 = blockIdx.y * 128, j0 = blockIdx.x * 128;
    __shared__ uint32_t Ah_s[128 * XS];
    __shared__ uint32_t Al_s[128 * XS];
    __shared__ uint32_t Bh_s[128 * XS];
    __shared__ uint32_t Bl_s[128 * XS];
    const float* f1 = &g_feat[0][(size_t)(b * NPG + i0) * 64];
    const float* f2 = &g_feat[1][(size_t)(b * NPG + j0) * 64];
    int tid = threadIdx.x;
    int warp = tid >> 5, lane = tid & 31;
    int wm = warp >> 2, wn = warp & 3;
    float acc[4][4][4];
#pragma unroll
    for (int mt = 0; mt < 4; mt++)
#pragma unroll
        for (int nt = 0; nt < 4; nt++)
#pragma unroll
            for (int j = 0; j < 4; j++) acc[mt][nt][j] = 0.0f;

    for (int k0 = 0; k0 < 64; k0 += 32) {
        for (int i = tid; i < 128 * 8; i += 256) {
            int r = i >> 3, q = i & 7;
            float4 va = *(const float4*)&f1[r * 64 + k0 + q * 4];
            float4 vb = *(const float4*)&f2[r * 64 + k0 + q * 4];
            uint32_t h0, l0, h1, l1;
            split2(va.x, va.y, h0, l0);
            split2(va.z, va.w, h1, l1);
            Ah_s[r * XS + q * 2] = h0;     Ah_s[r * XS + q * 2 + 1] = h1;
            Al_s[r * XS + q * 2] = l0;     Al_s[r * XS + q * 2 + 1] = l1;
            split2(vb.x, vb.y, h0, l0);
            split2(vb.z, vb.w, h1, l1);
            Bh_s[r * XS + q * 2] = h0;     Bh_s[r * XS + q * 2 + 1] = h1;
            Bl_s[r * XS + q * 2] = l0;     Bl_s[r * XS + q * 2 + 1] = l1;
        }
        __syncthreads();
#pragma unroll
        for (int s = 0; s < 2; s++) {
            int kb = s * 8 + (lane & 3);
            uint32_t ah[4][4], al[4][4], bh[4][2], bl[4][2];
#pragma unroll
            for (int mt = 0; mt < 4; mt++) {
                int arow = wm * 64 + mt * 16 + (lane >> 2);
                ah[mt][0] = Ah_s[arow * XS + kb];
                ah[mt][1] = Ah_s[(arow + 8) * XS + kb];
                ah[mt][2] = Ah_s[arow * XS + kb + 4];
                ah[mt][3] = Ah_s[(arow + 8) * XS + kb + 4];
                al[mt][0] = Al_s[arow * XS + kb];
                al[mt][1] = Al_s[(arow + 8) * XS + kb];
                al[mt][2] = Al_s[arow * XS + kb + 4];
                al[mt][3] = Al_s[(arow + 8) * XS + kb + 4];
            }
#pragma unroll
            for (int nt = 0; nt < 4; nt++) {
                int bnode = wn * 32 + nt * 8 + (lane >> 2);
                bh[nt][0] = Bh_s[bnode * XS + kb];
                bh[nt][1] = Bh_s[bnode * XS + kb + 4];
                bl[nt][0] = Bl_s[bnode * XS + kb];
                bl[nt][1] = Bl_s[bnode * XS + kb + 4];
            }
#pragma unroll
            for (int mt = 0; mt < 4; mt++)
#pragma unroll
                for (int nt = 0; nt < 4; nt++) {
                    mma_bf16(acc[mt][nt], ah[mt], bh[nt]);
                    mma_bf16(acc[mt][nt], ah[mt], bl[nt]);
                    mma_bf16(acc[mt][nt], al[mt], bh[nt]);
                }
        }
        __syncthreads();
    }
    float lmin = FLT_MAX, lmax = -FLT_MAX;
    __half* sp = &g_simh[(size_t)b * NPG * NPG];
    int col0 = (lane & 3) * 2;
#pragma unroll
    for (int mt = 0; mt < 4; mt++) {
        size_t r0 = (size_t)(i0 + wm * 64 + mt * 16 + (lane >> 2));
#pragma unroll
        for (int nt = 0; nt < 4; nt++) {
            int c = j0 + wn * 32 + nt * 8 + col0;
            float v0 = acc[mt][nt][0], v1 = acc[mt][nt][1];
            float v2 = acc[mt][nt][2], v3 = acc[mt][nt][3];
            lmin = fminf(lmin, fminf(fminf(v0, v1), fminf(v2, v3)));
            lmax = fmaxf(lmax, fmaxf(fmaxf(v0, v1), fmaxf(v2, v3)));
            *(__half2*)&sp[r0 * NPG + c] = __floats2half2_rn(v0, v1);
            *(__half2*)&sp[(r0 + 8) * NPG + c] = __floats2half2_rn(v2, v3);
        }
    }
    __shared__ float rmin[256], rmax[256];
    rmin[tid] = lmin;
    rmax[tid] = lmax;
    __syncthreads();
    for (int s = 128; s > 0; s >>= 1) {
        if (tid < s) {
            rmin[tid] = fminf(rmin[tid], rmin[tid + s]);
            rmax[tid] = fmaxf(rmax[tid], rmax[tid + s]);
        }
        __syncthreads();
    }
    if (tid == 0) {
        atomicMinFloat(&g_smin[b], rmin[0]);
        atomicMaxFloat(&g_smax[b], rmax[0]);
    }
}

// ---------------- histogram via threshold CDF, half2 SIMD compares ---------
__global__ void hist_k() {
    int b = blockIdx.y;
    int part = blockIdx.x;               // 8 parts per graph
    int t = threadIdx.x;
    int lane = t & 31, warp = t >> 5;    // 8 warps
    __shared__ __half2 thr_s[15];
    if (t < 15) {
        float vmin = sigmoidf_(g_smin[b]);
        float vmax = sigmoidf_(g_smax[b]);
        float width = (vmax - vmin) * (1.0f / D_BINS);
        float thr;
        if (width > 0.0f) {
            float bnd = vmin + (float)(t + 1) * width;
            thr = logf(bnd / (1.0f - bnd));
        } else {
            thr = FLT_MAX;
        }
        thr_s[t] = __float2half2_rn(thr);
    }
    __syncthreads();
    __half2 T2[15];
#pragma unroll
    for (int k = 0; k < 15; k++) T2[k] = thr_s[k];

    const uint4* qp = (const uint4*)&g_simh[(size_t)b * NPG * NPG] + part * 4096;
    __half2 C2[15];
#pragma unroll
    for (int k = 0; k < 15; k++) C2[k] = __float2half2_rn(0.0f);
    for (int i = t; i < 4096; i += 256) {
        uint4 q = qp[i];
        __half2 h0 = *(__half2*)&q.x;
        __half2 h1 = *(__half2*)&q.y;
        __half2 h2 = *(__half2*)&q.z;
        __half2 h3 = *(__half2*)&q.w;
#pragma unroll
        for (int k = 0; k < 15; k++) {
            C2[k] = __hadd2(C2[k], __hge2(h0, T2[k]));
            C2[k] = __hadd2(C2[k], __hge2(h1, T2[k]));
            C2[k] = __hadd2(C2[k], __hge2(h2, T2[k]));
            C2[k] = __hadd2(C2[k], __hge2(h3, T2[k]));
        }
    }
    __shared__ int red[8][15];
#pragma unroll
    for (int k = 0; k < 15; k++) {
        int c = (int)(__low2float(C2[k]) + __high2float(C2[k]));
#pragma unroll
        for (int o = 16; o; o >>= 1) c += __shfl_xor_sync(0xffffffffu, c, o);
        if (lane == 0) red[warp][k] = c;
    }
    __syncthreads();
    if (t < 15) {
        int s = 0;
#pragma unroll
        for (int w = 0; w < 8; w++) s += red[w][t];
        atomicAdd(&g_cdf[b][t], s);
    }
}

// ---------------- final head (one block per graph, 128 threads) ----------
__global__ void final_k(const float* __restrict__ Wt, const float* __restrict__ Wtb,
                        const float* __restrict__ tb, const float* __restrict__ W1,
                        const float* __restrict__ b1, const float* __restrict__ Ws,
                        const float* __restrict__ bs, float* __restrict__ out) {
    int b = blockIdx.x, t = threadIdx.x;
    __shared__ float p1s[64], p2s[64];
    __shared__ float scp[64 * 16];
    __shared__ float feat[32];
    __shared__ float hs[32];
    if (t < 64) {
        p1s[t] = g_pool[0][b * 64 + t];
        p2s[t] = g_pool[1][b * 64 + t];
    }
    __syncthreads();
    if (t < 64) {
        float s[16];
#pragma unroll
        for (int k = 0; k < 16; k++) s[k] = 0.0f;
        for (int j = 0; j < 64; j++) {
            float pj = p2s[j];
            const float* wp = &Wt[(size_t)(t * 64 + j) * 16];
#pragma unroll
            for (int k = 0; k < 16; k++) s[k] += wp[k] * pj;
        }
        float p1v = p1s[t];
#pragma unroll
        for (int k = 0; k < 16; k++) scp[t * 16 + k] = p1v * s[k];
    }
    __syncthreads();
    if (t < 16) {
        float acc = tb[t];
        for (int i = 0; i < 64; i++) acc += scp[i * 16 + t];
        float blk = 0.0f;
        for (int i = 0; i < 64; i++) blk += Wtb[t * 128 + i] * p1s[i];
        for (int i = 0; i < 64; i++) blk += Wtb[t * 128 + 64 + i] * p2s[i];
        float tv = acc + blk;
        feat[t] = fmaxf(tv, 0.0f);
        int C_lo = (t == 0) ? NPG * NPG : g_cdf[b][t - 1];
        int C_hi = (t == 15) ? 0 : g_cdf[b][t];
        feat[16 + t] = (float)(C_lo - C_hi) * (1.0f / ((float)NPG * (float)NPG));
    }
    __syncthreads();
    if (t < 32) {
        float acc = b1[t];
        for (int i = 0; i < 32; i++) acc += feat[i] * W1[i * 32 + t];
        hs[t] = fmaxf(acc, 0.0f);
    }
    __syncthreads();
    if (t == 0) {
        float acc = bs[0];
        for (int j = 0; j < 32; j++) acc += hs[j] * Ws[j];
        out[b] = sigmoidf_(acc);
    }
}

// ---------------- launcher ----------------
extern "C" void kernel_launch(void* const* d_in, const int* in_sizes, int n_in,
                              void* d_out, int out_size) {
    const float* x1  = (const float*)d_in[0];
    const float* x2  = (const float*)d_in[1];
    const int* ei1   = (const int*)d_in[2];
    const int* ei2   = (const int*)d_in[3];
    const float* Wc1 = (const float*)d_in[6];
    const float* bc1 = (const float*)d_in[7];
    const float* Wc2 = (const float*)d_in[8];
    const float* bc2 = (const float*)d_in[9];
    const float* Wc3 = (const float*)d_in[10];
    const float* bc3 = (const float*)d_in[11];
    const float* Watt = (const float*)d_in[12];
    const float* Wt  = (const float*)d_in[13];
    const float* Wtb = (const float*)d_in[14];
    const float* tb  = (const float*)d_in[15];
    const float* W1  = (const float*)d_in[16];
    const float* b1  = (const float*)d_in[17];
    const float* Ws  = (const float*)d_in[18];
    const float* bs  = (const float*)d_in[19];
    float* out = (float*)d_out;

    void* p;
    float *a0, *a1, *b0, *b1p, *f0, *f1;
    cudaGetSymbolAddress(&p, g_bufA);
    a0 = (float*)p; a1 = a0 + (size_t)NTOT * D_F1;
    cudaGetSymbolAddress(&p, g_bufB);
    b0 = (float*)p; b1p = b0 + (size_t)NTOT * D_F1;
    cudaGetSymbolAddress(&p, g_feat);
    f0 = (float*)p; f1 = f0 + (size_t)NTOT * D_F3;

    init_k<<<NTOT / 256, 256>>>();

    // CSR build for BOTH sides (batched over grid.y)
    deg_k<<<dim3(NEDGE / 256, 2), 256>>>(ei1 + NEDGE, ei2 + NEDGE);
    scanA_k<<<dim3(256, 2), 256>>>();   // also computes dinv
    scanC_k<<<dim3(256, 2), 256>>>();   // prefix via bsum reduce
    scatter_k<<<dim3(NEDGE / 256, 2), 256>>>(ei1, ei2);

    // conv pipeline, both sides per launch; agg = one block per graph (L1 reuse)
    agg_k<32, false, false><<<dim3(NB, 2), 1024>>>(x1, x2, nullptr, a0, a1);
    gemm_mma_k<32, 128, true, true><<<dim3(NTOT / 128, 2), 256>>>(a0, a1, Wc1, bc1, b0, b1p);

    gemm_mma_k<128, 96, false, false><<<dim3(NTOT / 128, 2), 256>>>(b0, b1p, Wc2, nullptr, a0, a1);
    agg_k<96, true, true><<<dim3(NB, 2), 1024>>>(a0, a1, bc2, b0, b1p);

    gemm_mma_k<96, 64, false, false><<<dim3(NTOT / 128, 2), 256>>>(b0, b1p, Wc3, nullptr, a0, a1);
    agg_k<64, true, false><<<dim3(NB, 2), 1024>>>(a0, a1, bc3, f0, f1);

    pool_k<<<dim3(NB, 2), 256>>>(Watt);

    sim_mma_k<<<dim3(4, 4, NB), 256>>>();
    hist_k<<<dim3(8, NB), 256>>>();
    final_k<<<NB, 128>>>(Wt, Wtb, tb, W1, b1, Ws, bs, out);
}

// round 13
// speedup vs baseline: 1.4443x; 1.0080x over previous
#include <cuda_runtime.h>
#include <cuda_fp16.h>
#include <math.h>
#include <cfloat>
#include <stdint.h>

// ---------------- problem dims (fixed) ----------------
#define NTOT  65536      // nodes per side (B*N)
#define NEDGE 524288     // edges per side
#define NB    128        // graphs
#define NPG   512        // nodes per graph
#define D_F1  128
#define D_F2  96
#define D_F3  64
#define D_BINS 16

// ---------------- device scratch (per-side slabs for batched launches) -----
__device__ float g_bufA[2][NTOT * D_F1];
__device__ float g_bufB[2][NTOT * D_F1];
__device__ float g_feat[2][NTOT * D_F3];
__device__ float g_dinv[2][NTOT];
__device__ int   g_degi[2][NTOT];
__device__ int   g_row[2][NTOT + 1];
__device__ int   g_cursor[2][NTOT];
__device__ int   g_bsum[2][256];
__device__ int2  g_epack[2][NEDGE];                  // {src, norm bits}
__device__ __half g_simh[(size_t)NB * NPG * NPG];   // fp16 similarity scores
__device__ float g_smin[NB];
__device__ float g_smax[NB];
__device__ float g_pool[2][NB * D_F3];

__device__ __forceinline__ float sigmoidf_(float x) { return 1.0f / (1.0f + expf(-x)); }

__device__ __forceinline__ void atomicMinFloat(float* addr, float val) {
    int old = __float_as_int(*addr);
    while (__int_as_float(old) > val) {
        int assumed = old;
        old = atomicCAS((int*)addr, assumed, __float_as_int(val));
        if (old == assumed) break;
    }
}
__device__ __forceinline__ void atomicMaxFloat(float* addr, float val) {
    int old = __float_as_int(*addr);
    while (__int_as_float(old) < val) {
        int assumed = old;
        old = atomicCAS((int*)addr, assumed, __float_as_int(val));
        if (old == assumed) break;
    }
}

// ---------------- bf16x3 helpers (fp32 emulation via bf16 split) -----------
__device__ __forceinline__ void split2(float x0, float x1, uint32_t& h, uint32_t& l) {
    asm("cvt.rn.bf16x2.f32 %0, %1, %2;" : "=r"(h) : "f"(x1), "f"(x0));
    float r0 = x0 - __uint_as_float(h << 16);
    float r1 = x1 - __uint_as_float(h & 0xffff0000u);
    asm("cvt.rn.bf16x2.f32 %0, %1, %2;" : "=r"(l) : "f"(r1), "f"(r0));
}
__device__ __forceinline__ void mma_bf16(float* d, const uint32_t* a, const uint32_t* b) {
    asm volatile(
        "mma.sync.aligned.m16n8k16.row.col.f32.bf16.bf16.f32 "
        "{%0,%1,%2,%3}, {%4,%5,%6,%7}, {%8,%9}, {%0,%1,%2,%3};\n"
        : "+f"(d[0]), "+f"(d[1]), "+f"(d[2]), "+f"(d[3])
        : "r"(a[0]), "r"(a[1]), "r"(a[2]), "r"(a[3]), "r"(b[0]), "r"(b[1]));
}

// block-wide exclusive scan of 256 ints (one value per thread)
__device__ __forceinline__ int block_exscan_256(int v, int* sm8) {
    int lane = threadIdx.x & 31, w = threadIdx.x >> 5;
    int x = v;
#pragma unroll
    for (int o = 1; o < 32; o <<= 1) {
        int y = __shfl_up_sync(0xffffffffu, x, o);
        if (lane >= o) x += y;
    }
    if (lane == 31) sm8[w] = x;
    __syncthreads();
    if (threadIdx.x < 8) {
        int s = sm8[threadIdx.x];
#pragma unroll
        for (int o = 1; o < 8; o <<= 1) {
            int y = __shfl_up_sync(0xffu, s, o);
            if ((int)threadIdx.x >= o) s += y;
        }
        sm8[threadIdx.x] = s;
    }
    __syncthreads();
    int woff = w ? sm8[w - 1] : 0;
    return woff + x - v;
}

// ---------------- init ----------------
__global__ void init_k() {
    int i = blockIdx.x * blockDim.x + threadIdx.x;
    if (i < NTOT) { g_degi[0][i] = 0; g_degi[1][i] = 0; }
    if (i < NB) { g_smin[i] = FLT_MAX; g_smax[i] = -FLT_MAX; }
}

// ---------------- degree (both sides via grid.y) ----------------
__global__ void deg_k(const int* __restrict__ dst0, const int* __restrict__ dst1) {
    int side = blockIdx.y;
    const int* dst = side ? dst1 : dst0;
    int e = blockIdx.x * blockDim.x + threadIdx.x;
    if (e < NEDGE) atomicAdd(&g_degi[side][dst[e]], 1);
}

// ---------------- 2-phase parallel scan (A computes dinv + block sums) -----
__global__ void scanA_k() {
    int side = blockIdx.y;
    int i = blockIdx.x * 256 + threadIdx.x;
    int v = g_degi[side][i];
    g_dinv[side][i] = rsqrtf((float)v + 1.0f);
#pragma unroll
    for (int o = 16; o; o >>= 1) v += __shfl_xor_sync(0xffffffffu, v, o);
    __shared__ int sm[8];
    if ((threadIdx.x & 31) == 0) sm[threadIdx.x >> 5] = v;
    __syncthreads();
    if (threadIdx.x == 0) {
        int s = 0;
#pragma unroll
        for (int j = 0; j < 8; j++) s += sm[j];
        g_bsum[side][blockIdx.x] = s;
    }
}
// scanC: per-block exclusive scan; prefix computed by reducing g_bsum[0..bid)
__global__ void scanC_k() {
    int side = blockIdx.y;
    int bid = blockIdx.x;
    int t = threadIdx.x;
    int lane = t & 31, w = t >> 5;
    int pv = (t < bid) ? g_bsum[side][t] : 0;
#pragma unroll
    for (int o = 16; o; o >>= 1) pv += __shfl_xor_sync(0xffffffffu, pv, o);
    __shared__ int rsm[8];
    if (lane == 0) rsm[w] = pv;
    __syncthreads();
    __shared__ int prefix_s;
    if (t == 0) {
        int s = 0;
#pragma unroll
        for (int j = 0; j < 8; j++) s += rsm[j];
        prefix_s = s;
    }
    __syncthreads();
    int prefix = prefix_s;
    int i = bid * 256 + t;
    int d = g_degi[side][i];
    __shared__ int sm[8];
    int ex = block_exscan_256(d, sm);
    int off = prefix + ex;
    g_row[side][i] = off;
    g_cursor[side][i] = off;
    if (i == NTOT - 1) g_row[side][NTOT] = NEDGE;
}

// ---------------- scatter edges into CSR order (packed src+norm) -----------
__global__ void scatter_k(const int* __restrict__ ei0, const int* __restrict__ ei1) {
    int side = blockIdx.y;
    const int* ei = side ? ei1 : ei0;
    const int* src = ei;
    const int* dst = ei + NEDGE;
    int e = blockIdx.x * blockDim.x + threadIdx.x;
    if (e >= NEDGE) return;
    int s = src[e], d = dst[e];
    int pos = atomicAdd(&g_cursor[side][d], 1);
    float nm = g_dinv[side][s] * g_dinv[side][d];
    g_epack[side][pos] = make_int2(s, __float_as_int(nm));
}

// ---------------- graph-per-block aggregation (L1-resident gathers) --------
template <int OUT, bool BIAS, bool RELU>
__global__ void agg_k(const float* __restrict__ xw0, const float* __restrict__ xw1,
                      const float* __restrict__ bias,
                      float* __restrict__ out0, float* __restrict__ out1) {
    constexpr int C4 = OUT / 4;
    int side = blockIdx.y;
    const float* xw = side ? xw1 : xw0;
    float* out = side ? out1 : out0;
    int base = blockIdx.x * NPG;
    const float4* xw4 = (const float4*)xw;
    float4* out4 = (float4*)out;
    for (int wi = threadIdx.x; wi < NPG * C4; wi += blockDim.x) {
        int node = base + wi / C4;
        int chunk = wi % C4;
        float dv = g_dinv[side][node];
        float dv2 = dv * dv;
        float4 v = xw4[(size_t)node * C4 + chunk];
        float4 acc = make_float4(v.x * dv2, v.y * dv2, v.z * dv2, v.w * dv2);
        int beg = g_row[side][node], end = g_row[side][node + 1];
        for (int e = beg; e < end; e++) {
            int2 ep = g_epack[side][e];
            float nm = __int_as_float(ep.y);
            float4 u = xw4[(size_t)ep.x * C4 + chunk];
            acc.x += u.x * nm; acc.y += u.y * nm; acc.z += u.z * nm; acc.w += u.w * nm;
        }
        if (BIAS) {
            acc.x += bias[chunk * 4 + 0];
            acc.y += bias[chunk * 4 + 1];
            acc.z += bias[chunk * 4 + 2];
            acc.w += bias[chunk * 4 + 3];
        }
        if (RELU) {
            acc.x = fmaxf(acc.x, 0.f); acc.y = fmaxf(acc.y, 0.f);
            acc.z = fmaxf(acc.z, 0.f); acc.w = fmaxf(acc.w, 0.f);
        }
        out4[(size_t)node * C4 + chunk] = acc;
    }
}

// ---------------- agg3 + attention pool fused (one block per graph) --------
// OUT=64 + bias; result to global feat AND smem slab; pool runs on the slab.
__global__ void agg_pool_k(const float* __restrict__ xw0, const float* __restrict__ xw1,
                           const float* __restrict__ bias,
                           float* __restrict__ out0, float* __restrict__ out1,
                           const float* __restrict__ Watt) {
    constexpr int OUT = 64, C4 = 16;
    extern __shared__ float sfeat[];       // NPG*64 floats = 128 KB
    int side = blockIdx.y;
    int b = blockIdx.x;
    const float* xw = side ? xw1 : xw0;
    float* out = side ? out1 : out0;
    int base = b * NPG;
    const float4* xw4 = (const float4*)xw;
    float4* out4 = (float4*)out;
    float4* sf4 = (float4*)sfeat;
    int t = threadIdx.x;                    // 1024

    // ---- aggregation ----
    for (int wi = t; wi < NPG * C4; wi += 1024) {
        int node = base + wi / C4;
        int chunk = wi % C4;
        float dv = g_dinv[side][node];
        float dv2 = dv * dv;
        float4 v = xw4[(size_t)node * C4 + chunk];
        float4 acc = make_float4(v.x * dv2, v.y * dv2, v.z * dv2, v.w * dv2);
        int beg = g_row[side][node], end = g_row[side][node + 1];
        for (int e = beg; e < end; e++) {
            int2 ep = g_epack[side][e];
            float nm = __int_as_float(ep.y);
            float4 u = xw4[(size_t)ep.x * C4 + chunk];
            acc.x += u.x * nm; acc.y += u.y * nm; acc.z += u.z * nm; acc.w += u.w * nm;
        }
        acc.x += bias[chunk * 4 + 0];
        acc.y += bias[chunk * 4 + 1];
        acc.z += bias[chunk * 4 + 2];
        acc.w += bias[chunk * 4 + 3];
        out4[(size_t)node * C4 + chunk] = acc;
        sf4[wi] = acc;
    }
    __syncthreads();

    // ---- attention pooling on the smem slab ----
    __shared__ float p16[16][64];
    __shared__ float meanc[64];
    __shared__ float ctx[64];
    __shared__ float wsum[32][64];
    int d = t & 63, g = t >> 6;             // g in [0,16)
    float loc = 0.0f;
    for (int r = g; r < NPG; r += 16) loc += sfeat[r * 64 + d];
    p16[g][d] = loc;
    __syncthreads();
    if (t < 64) {
        float s = 0.0f;
#pragma unroll
        for (int j = 0; j < 16; j++) s += p16[j][t];
        meanc[t] = s * (1.0f / NPG);
    }
    __syncthreads();
    if (t < 64) {
        float c = 0.0f;
        for (int i = 0; i < 64; i++) c += meanc[i] * Watt[i * 64 + t];
        ctx[t] = tanhf(c);
    }
    __syncthreads();
    int w = t >> 5, l = t & 31;             // 32 warps, 16 rows each
    float a0 = 0.0f, a1 = 0.0f;
    float c0 = ctx[l], c1 = ctx[l + 32];
    for (int r = w * 16; r < w * 16 + 16; r++) {
        float v0 = sfeat[r * 64 + l], v1 = sfeat[r * 64 + 32 + l];
        float dp = v0 * c0 + v1 * c1;
#pragma unroll
        for (int o = 16; o; o >>= 1) dp += __shfl_xor_sync(0xffffffffu, dp, o);
        float coef = sigmoidf_(dp);
        a0 += v0 * coef;
        a1 += v1 * coef;
    }
    wsum[w][l] = a0;
    wsum[w][l + 32] = a1;
    __syncthreads();
    if (t < 64) {
        float s = 0.0f;
#pragma unroll
        for (int w2 = 0; w2 < 32; w2++) s += wsum[w2][t];
        g_pool[side][b * 64 + t] = s;
    }
}

// ---------------- bf16x3 tensor-core GEMM (both sides via grid.y) ----------
template <int KIN, int NOUT, bool BIAS, bool RELU>
__global__ void gemm_mma_k(const float* __restrict__ x0, const float* __restrict__ x1,
                           const float* __restrict__ W, const float* __restrict__ bias,
                           float* __restrict__ out0, float* __restrict__ out1) {
    constexpr int KC = 32;
    constexpr int KP = KC / 2;
    constexpr int NT = NOUT / 8;
    constexpr int XS = 20;
    constexpr int WS = 20;
    __shared__ uint32_t Xh[128 * XS];
    __shared__ uint32_t Xl[128 * XS];
    __shared__ uint32_t Wh[NOUT * WS];
    __shared__ uint32_t Wl[NOUT * WS];
    int side = blockIdx.y;
    const float* x = side ? x1 : x0;
    float* out = side ? out1 : out0;
    int tid = threadIdx.x;
    int warp = tid >> 5, lane = tid & 31;
    size_t m0 = (size_t)blockIdx.x * 128;
    float acc[NT][4];
#pragma unroll
    for (int i = 0; i < NT; i++)
#pragma unroll
        for (int j = 0; j < 4; j++) acc[i][j] = 0.0f;

    for (int k0 = 0; k0 < KIN; k0 += KC) {
        for (int i = tid; i < 128 * 8; i += 256) {
            int r = i >> 3, q = i & 7;
            float4 v = *(const float4*)&x[(m0 + r) * KIN + k0 + q * 4];
            uint32_t h0, l0, h1, l1;
            split2(v.x, v.y, h0, l0);
            split2(v.z, v.w, h1, l1);
            Xh[r * XS + q * 2] = h0;     Xh[r * XS + q * 2 + 1] = h1;
            Xl[r * XS + q * 2] = l0;     Xl[r * XS + q * 2 + 1] = l1;
        }
        for (int i = tid; i < NOUT * KP; i += 256) {
            int kp = i / NOUT, n = i % NOUT;
            float w0 = W[(size_t)(k0 + 2 * kp) * NOUT + n];
            float w1 = W[(size_t)(k0 + 2 * kp + 1) * NOUT + n];
            uint32_t h, l;
            split2(w0, w1, h, l);
            Wh[n * WS + kp] = h;
            Wl[n * WS + kp] = l;
        }
        __syncthreads();
#pragma unroll
        for (int s = 0; s < 2; s++) {
            int kb = s * 8 + (lane & 3);
            uint32_t ah[4], al[4];
            int arow = warp * 16 + (lane >> 2);
            ah[0] = Xh[arow * XS + kb];           al[0] = Xl[arow * XS + kb];
            ah[1] = Xh[(arow + 8) * XS + kb];     al[1] = Xl[(arow + 8) * XS + kb];
            ah[2] = Xh[arow * XS + kb + 4];       al[2] = Xl[arow * XS + kb + 4];
            ah[3] = Xh[(arow + 8) * XS + kb + 4]; al[3] = Xl[(arow + 8) * XS + kb + 4];
            int bn = lane >> 2;
#pragma unroll
            for (int nt = 0; nt < NT; nt++) {
                uint32_t bh[2], bl[2];
                int nb = (nt * 8 + bn) * WS;
                bh[0] = Wh[nb + kb]; bh[1] = Wh[nb + kb + 4];
                bl[0] = Wl[nb + kb]; bl[1] = Wl[nb + kb + 4];
                mma_bf16(acc[nt], ah, bh);
                mma_bf16(acc[nt], ah, bl);
                mma_bf16(acc[nt], al, bh);
            }
        }
        __syncthreads();
    }
    size_t row = m0 + warp * 16 + (lane >> 2);
    int col0 = (lane & 3) * 2;
#pragma unroll
    for (int nt = 0; nt < NT; nt++) {
        int c = nt * 8 + col0;
        float b0 = BIAS ? bias[c] : 0.0f, b1 = BIAS ? bias[c + 1] : 0.0f;
        float v0 = acc[nt][0] + b0, v1 = acc[nt][1] + b1;
        float v2 = acc[nt][2] + b0, v3 = acc[nt][3] + b1;
        if (RELU) {
            v0 = fmaxf(v0, 0.f); v1 = fmaxf(v1, 0.f);
            v2 = fmaxf(v2, 0.f); v3 = fmaxf(v3, 0.f);
        }
        *(float2*)&out[row * NOUT + c] = make_float2(v0, v1);
        *(float2*)&out[(row + 8) * NOUT + c] = make_float2(v2, v3);
    }
}

// ---------------- similarity via bf16x3 mma, 128x128 tile, fp16 store ------
__global__ void sim_mma_k() {
    constexpr int XS = 20;
    int b = blockIdx.z;
    int i0 = blockIdx.y * 128, j0 = blockIdx.x * 128;
    __shared__ uint32_t Ah_s[128 * XS];
    __shared__ uint32_t Al_s[128 * XS];
    __shared__ uint32_t Bh_s[128 * XS];
    __shared__ uint32_t Bl_s[128 * XS];
    const float* f1 = &g_feat[0][(size_t)(b * NPG + i0) * 64];
    const float* f2 = &g_feat[1][(size_t)(b * NPG + j0) * 64];
    int tid = threadIdx.x;
    int warp = tid >> 5, lane = tid & 31;
    int wm = warp >> 2, wn = warp & 3;
    float acc[4][4][4];
#pragma unroll
    for (int mt = 0; mt < 4; mt++)
#pragma unroll
        for (int nt = 0; nt < 4; nt++)
#pragma unroll
            for (int j = 0; j < 4; j++) acc[mt][nt][j] = 0.0f;

    for (int k0 = 0; k0 < 64; k0 += 32) {
        for (int i = tid; i < 128 * 8; i += 256) {
            int r = i >> 3, q = i & 7;
            float4 va = *(const float4*)&f1[r * 64 + k0 + q * 4];
            float4 vb = *(const float4*)&f2[r * 64 + k0 + q * 4];
            uint32_t h0, l0, h1, l1;
            split2(va.x, va.y, h0, l0);
            split2(va.z, va.w, h1, l1);
            Ah_s[r * XS + q * 2] = h0;     Ah_s[r * XS + q * 2 + 1] = h1;
            Al_s[r * XS + q * 2] = l0;     Al_s[r * XS + q * 2 + 1] = l1;
            split2(vb.x, vb.y, h0, l0);
            split2(vb.z, vb.w, h1, l1);
            Bh_s[r * XS + q * 2] = h0;     Bh_s[r * XS + q * 2 + 1] = h1;
            Bl_s[r * XS + q * 2] = l0;     Bl_s[r * XS + q * 2 + 1] = l1;
        }
        __syncthreads();
#pragma unroll
        for (int s = 0; s < 2; s++) {
            int kb = s * 8 + (lane & 3);
            uint32_t ah[4][4], al[4][4], bh[4][2], bl[4][2];
#pragma unroll
            for (int mt = 0; mt < 4; mt++) {
                int arow = wm * 64 + mt * 16 + (lane >> 2);
                ah[mt][0] = Ah_s[arow * XS + kb];
                ah[mt][1] = Ah_s[(arow + 8) * XS + kb];
                ah[mt][2] = Ah_s[arow * XS + kb + 4];
                ah[mt][3] = Ah_s[(arow + 8) * XS + kb + 4];
                al[mt][0] = Al_s[arow * XS + kb];
                al[mt][1] = Al_s[(arow + 8) * XS + kb];
                al[mt][2] = Al_s[arow * XS + kb + 4];
                al[mt][3] = Al_s[(arow + 8) * XS + kb + 4];
            }
#pragma unroll
            for (int nt = 0; nt < 4; nt++) {
                int bnode = wn * 32 + nt * 8 + (lane >> 2);
                bh[nt][0] = Bh_s[bnode * XS + kb];
                bh[nt][1] = Bh_s[bnode * XS + kb + 4];
                bl[nt][0] = Bl_s[bnode * XS + kb];
                bl[nt][1] = Bl_s[bnode * XS + kb + 4];
            }
#pragma unroll
            for (int mt = 0; mt < 4; mt++)
#pragma unroll
                for (int nt = 0; nt < 4; nt++) {
                    mma_bf16(acc[mt][nt], ah[mt], bh[nt]);
                    mma_bf16(acc[mt][nt], ah[mt], bl[nt]);
                    mma_bf16(acc[mt][nt], al[mt], bh[nt]);
                }
        }
        __syncthreads();
    }
    float lmin = FLT_MAX, lmax = -FLT_MAX;
    __half* sp = &g_simh[(size_t)b * NPG * NPG];
    int col0 = (lane & 3) * 2;
#pragma unroll
    for (int mt = 0; mt < 4; mt++) {
        size_t r0 = (size_t)(i0 + wm * 64 + mt * 16 + (lane >> 2));
#pragma unroll
        for (int nt = 0; nt < 4; nt++) {
            int c = j0 + wn * 32 + nt * 8 + col0;
            float v0 = acc[mt][nt][0], v1 = acc[mt][nt][1];
            float v2 = acc[mt][nt][2], v3 = acc[mt][nt][3];
            lmin = fminf(lmin, fminf(fminf(v0, v1), fminf(v2, v3)));
            lmax = fmaxf(lmax, fmaxf(fmaxf(v0, v1), fmaxf(v2, v3)));
            *(__half2*)&sp[r0 * NPG + c] = __floats2half2_rn(v0, v1);
            *(__half2*)&sp[(r0 + 8) * NPG + c] = __floats2half2_rn(v2, v3);
        }
    }
    __shared__ float rmin[256], rmax[256];
    rmin[tid] = lmin;
    rmax[tid] = lmax;
    __syncthreads();
    for (int s = 128; s > 0; s >>= 1) {
        if (tid < s) {
            rmin[tid] = fminf(rmin[tid], rmin[tid + s]);
            rmax[tid] = fmaxf(rmax[tid], rmax[tid + s]);
        }
        __syncthreads();
    }
    if (tid == 0) {
        atomicMinFloat(&g_smin[b], rmin[0]);
        atomicMaxFloat(&g_smax[b], rmax[0]);
    }
}

// ---------------- histogram (threshold CDF, half2) + final head fused ------
// one block of 1024 threads per graph
__global__ void hist_final_k(const float* __restrict__ Wt, const float* __restrict__ Wtb,
                             const float* __restrict__ tb, const float* __restrict__ W1,
                             const float* __restrict__ b1, const float* __restrict__ Ws,
                             const float* __restrict__ bs, float* __restrict__ out) {
    int b = blockIdx.x;
    int t = threadIdx.x;
    int lane = t & 31, warp = t >> 5;     // 32 warps
    __shared__ __half2 thr_s[15];
    if (t < 15) {
        float vmin = sigmoidf_(g_smin[b]);
        float vmax = sigmoidf_(g_smax[b]);
        float width = (vmax - vmin) * (1.0f / D_BINS);
        float thr;
        if (width > 0.0f) {
            float bnd = vmin + (float)(t + 1) * width;
            thr = logf(bnd / (1.0f - bnd));
        } else {
            thr = FLT_MAX;
        }
        thr_s[t] = __float2half2_rn(thr);
    }
    __syncthreads();
    __half2 T2[15];
#pragma unroll
    for (int k = 0; k < 15; k++) T2[k] = thr_s[k];

    const uint4* qp = (const uint4*)&g_simh[(size_t)b * NPG * NPG];
    __half2 C2[15];
#pragma unroll
    for (int k = 0; k < 15; k++) C2[k] = __float2half2_rn(0.0f);
    // 32768 uint4 per graph / 1024 threads = 32 iters; per-half count <= 128 (exact fp16)
    for (int i = t; i < 32768; i += 1024) {
        uint4 q = qp[i];
        __half2 h0 = *(__half2*)&q.x;
        __half2 h1 = *(__half2*)&q.y;
        __half2 h2 = *(__half2*)&q.z;
        __half2 h3 = *(__half2*)&q.w;
#pragma unroll
        for (int k = 0; k < 15; k++) {
            C2[k] = __hadd2(C2[k], __hge2(h0, T2[k]));
            C2[k] = __hadd2(C2[k], __hge2(h1, T2[k]));
            C2[k] = __hadd2(C2[k], __hge2(h2, T2[k]));
            C2[k] = __hadd2(C2[k], __hge2(h3, T2[k]));
        }
    }
    __shared__ int red[32][16];
#pragma unroll
    for (int k = 0; k < 15; k++) {
        int c = (int)(__low2float(C2[k]) + __high2float(C2[k]));
#pragma unroll
        for (int o = 16; o; o >>= 1) c += __shfl_xor_sync(0xffffffffu, c, o);
        if (lane == 0) red[warp][k] = c;
    }
    __syncthreads();
    __shared__ int cdf_s[15];
    if (t < 15) {
        int s = 0;
#pragma unroll
        for (int w = 0; w < 32; w++) s += red[w][t];
        cdf_s[t] = s;
    }

    // ---- final head ----
    __shared__ float p1s[64], p2s[64];
    __shared__ float scp[64 * 16];
    __shared__ float feat[32];
    __shared__ float hs[32];
    if (t < 64) {
        p1s[t] = g_pool[0][b * 64 + t];
        p2s[t] = g_pool[1][b * 64 + t];
    }
    __syncthreads();
    if (t < 64) {
        float s[16];
#pragma unroll
        for (int k = 0; k < 16; k++) s[k] = 0.0f;
        for (int j = 0; j < 64; j++) {
            float pj = p2s[j];
            const float* wp = &Wt[(size_t)(t * 64 + j) * 16];
#pragma unroll
            for (int k = 0; k < 16; k++) s[k] += wp[k] * pj;
        }
        float p1v = p1s[t];
#pragma unroll
        for (int k = 0; k < 16; k++) scp[t * 16 + k] = p1v * s[k];
    }
    __syncthreads();
    if (t < 16) {
        float acc = tb[t];
        for (int i = 0; i < 64; i++) acc += scp[i * 16 + t];
        float blk = 0.0f;
        for (int i = 0; i < 64; i++) blk += Wtb[t * 128 + i] * p1s[i];
        for (int i = 0; i < 64; i++) blk += Wtb[t * 128 + 64 + i] * p2s[i];
        float tv = acc + blk;
        feat[t] = fmaxf(tv, 0.0f);
        int C_lo = (t == 0) ? NPG * NPG : cdf_s[t - 1];
        int C_hi = (t == 15) ? 0 : cdf_s[t];
        feat[16 + t] = (float)(C_lo - C_hi) * (1.0f / ((float)NPG * (float)NPG));
    }
    __syncthreads();
    if (t < 32) {
        float acc = b1[t];
        for (int i = 0; i < 32; i++) acc += feat[i] * W1[i * 32 + t];
        hs[t] = fmaxf(acc, 0.0f);
    }
    __syncthreads();
    if (t == 0) {
        float acc = bs[0];
        for (int j = 0; j < 32; j++) acc += hs[j] * Ws[j];
        out[b] = sigmoidf_(acc);
    }
}

// ---------------- launcher ----------------
extern "C" void kernel_launch(void* const* d_in, const int* in_sizes, int n_in,
                              void* d_out, int out_size) {
    const float* x1  = (const float*)d_in[0];
    const float* x2  = (const float*)d_in[1];
    const int* ei1   = (const int*)d_in[2];
    const int* ei2   = (const int*)d_in[3];
    const float* Wc1 = (const float*)d_in[6];
    const float* bc1 = (const float*)d_in[7];
    const float* Wc2 = (const float*)d_in[8];
    const float* bc2 = (const float*)d_in[9];
    const float* Wc3 = (const float*)d_in[10];
    const float* bc3 = (const float*)d_in[11];
    const float* Watt = (const float*)d_in[12];
    const float* Wt  = (const float*)d_in[13];
    const float* Wtb = (const float*)d_in[14];
    const float* tb  = (const float*)d_in[15];
    const float* W1  = (const float*)d_in[16];
    const float* b1  = (const float*)d_in[17];
    const float* Ws  = (const float*)d_in[18];
    const float* bs  = (const float*)d_in[19];
    float* out = (float*)d_out;

    void* p;
    float *a0, *a1, *b0, *b1p, *f0, *f1;
    cudaGetSymbolAddress(&p, g_bufA);
    a0 = (float*)p; a1 = a0 + (size_t)NTOT * D_F1;
    cudaGetSymbolAddress(&p, g_bufB);
    b0 = (float*)p; b1p = b0 + (size_t)NTOT * D_F1;
    cudaGetSymbolAddress(&p, g_feat);
    f0 = (float*)p; f1 = f0 + (size_t)NTOT * D_F3;

    // opt-in to 128 KB dynamic smem for the fused agg+pool kernel (idempotent)
    cudaFuncSetAttribute(agg_pool_k, cudaFuncAttributeMaxDynamicSharedMemorySize,
                         NPG * D_F3 * 4);

    init_k<<<NTOT / 256, 256>>>();

    // CSR build for BOTH sides (batched over grid.y)
    deg_k<<<dim3(NEDGE / 256, 2), 256>>>(ei1 + NEDGE, ei2 + NEDGE);
    scanA_k<<<dim3(256, 2), 256>>>();   // also computes dinv
    scanC_k<<<dim3(256, 2), 256>>>();   // prefix via bsum reduce
    scatter_k<<<dim3(NEDGE / 256, 2), 256>>>(ei1, ei2);

    // conv pipeline, both sides per launch; agg = one block per graph (L1 reuse)
    agg_k<32, false, false><<<dim3(NB, 2), 1024>>>(x1, x2, nullptr, a0, a1);
    gemm_mma_k<32, 128, true, true><<<dim3(NTOT / 128, 2), 256>>>(a0, a1, Wc1, bc1, b0, b1p);

    gemm_mma_k<128, 96, false, false><<<dim3(NTOT / 128, 2), 256>>>(b0, b1p, Wc2, nullptr, a0, a1);
    agg_k<96, true, true><<<dim3(NB, 2), 1024>>>(a0, a1, bc2, b0, b1p);

    gemm_mma_k<96, 64, false, false><<<dim3(NTOT / 128, 2), 256>>>(b0, b1p, Wc3, nullptr, a0, a1);
    // agg3 + pool fused (writes g_feat and g_pool)
    agg_pool_k<<<dim3(NB, 2), 1024, NPG * D_F3 * 4>>>(a0, a1, bc3, f0, f1, Watt);

    sim_mma_k<<<dim3(4, 4, NB), 256>>>();
    hist_final_k<<<NB, 1024>>>(Wt, Wtb, tb, W1, b1, Ws, bs, out);
}